// round 1
// baseline (speedup 1.0000x reference)
#include <cuda_runtime.h>

#define BB 2
#define TT 2048
#define CC 2048
#define HH 16
#define DD 128
#define MTOT (BB * TT)   // 4096

// Scratch (allocation-free: __device__ globals)
__device__ float g_Q[(size_t)MTOT * CC];  // 32 MB
__device__ float g_K[(size_t)MTOT * DD];  //  2 MB
__device__ float g_V[(size_t)MTOT * DD];  //  2 MB
__device__ float g_O[(size_t)MTOT * CC];  // 32 MB

// ---------------------------------------------------------------------------
// Tiled fp32 GEMM: Out[M,N] = A[M,K] @ W[K,N] + bias[N]
// BM=BN=128, BK=16, 256 threads, 8x8 microtile (cols split 4tx / 64+4tx for
// conflict-free float4 smem reads). M,N,K multiples of 128/16 (true here).
// ---------------------------------------------------------------------------
__global__ __launch_bounds__(256) void gemm_bias_kernel(
    const float* __restrict__ A, const float* __restrict__ W,
    const float* __restrict__ bias, float* __restrict__ Out,
    int M, int N, int K)
{
    __shared__ float As[16][132];   // transposed: As[k][m], pad 4
    __shared__ float Bs[16][128];   // Bs[k][n]

    const int tid = threadIdx.x;
    const int m0 = blockIdx.y * 128;
    const int n0 = blockIdx.x * 128;
    const int ty = tid >> 4;        // 0..15 -> rows 8*ty..8*ty+7
    const int tx = tid & 15;        // 0..15 -> cols 4*tx.. and 64+4*tx..

    float acc[8][8];
#pragma unroll
    for (int i = 0; i < 8; i++)
#pragma unroll
        for (int j = 0; j < 8; j++) acc[i][j] = 0.f;

    for (int k0 = 0; k0 < K; k0 += 16) {
        // A tile: 128 rows x 16 k (float4 global, scatter-transpose to smem)
#pragma unroll
        for (int l = 0; l < 2; l++) {
            int idx4 = tid + l * 256;
            int row  = idx4 >> 2;
            int kc   = (idx4 & 3) << 2;
            float4 v = *(const float4*)(A + (size_t)(m0 + row) * K + k0 + kc);
            As[kc + 0][row] = v.x;
            As[kc + 1][row] = v.y;
            As[kc + 2][row] = v.z;
            As[kc + 3][row] = v.w;
        }
        // B tile: 16 k x 128 n (float4 both sides)
#pragma unroll
        for (int l = 0; l < 2; l++) {
            int idx4 = tid + l * 256;
            int kk   = idx4 >> 5;
            int cc4  = (idx4 & 31) << 2;
            *(float4*)&Bs[kk][cc4] =
                *(const float4*)(W + (size_t)(k0 + kk) * N + n0 + cc4);
        }
        __syncthreads();

#pragma unroll
        for (int kk = 0; kk < 16; kk++) {
            float4 a0 = *(float4*)&As[kk][8 * ty];
            float4 a1 = *(float4*)&As[kk][8 * ty + 4];
            float4 b0 = *(float4*)&Bs[kk][4 * tx];
            float4 b1 = *(float4*)&Bs[kk][64 + 4 * tx];
            float a[8] = {a0.x, a0.y, a0.z, a0.w, a1.x, a1.y, a1.z, a1.w};
            float bb[8] = {b0.x, b0.y, b0.z, b0.w, b1.x, b1.y, b1.z, b1.w};
#pragma unroll
            for (int i = 0; i < 8; i++)
#pragma unroll
                for (int j = 0; j < 8; j++)
                    acc[i][j] += a[i] * bb[j];
        }
        __syncthreads();
    }

    float4 bi0 = *(const float4*)(bias + n0 + 4 * tx);
    float4 bi1 = *(const float4*)(bias + n0 + 64 + 4 * tx);
#pragma unroll
    for (int i = 0; i < 8; i++) {
        size_t row = (size_t)(m0 + 8 * ty + i);
        float4 r0 = make_float4(acc[i][0] + bi0.x, acc[i][1] + bi0.y,
                                acc[i][2] + bi0.z, acc[i][3] + bi0.w);
        float4 r1 = make_float4(acc[i][4] + bi1.x, acc[i][5] + bi1.y,
                                acc[i][6] + bi1.z, acc[i][7] + bi1.w);
        *(float4*)(Out + row * N + n0 + 4 * tx)      = r0;
        *(float4*)(Out + row * N + n0 + 64 + 4 * tx) = r1;
    }
}

// ---------------------------------------------------------------------------
// RoPE: buf rows are [row][2*pairs]; pair p of row uses cos/sin[t, p & 63].
// Flat element offset of pair = 2*idx.  log2pairs: 10 for Q (1024), 6 for K.
// ---------------------------------------------------------------------------
__global__ __launch_bounds__(256) void rope_kernel(
    float* __restrict__ buf, const float* __restrict__ cs,
    const float* __restrict__ sn, int log2pairs)
{
    int idx = blockIdx.x * blockDim.x + threadIdx.x;
    int row = idx >> log2pairs;
    int p   = idx & ((1 << log2pairs) - 1);
    int f   = p & 63;
    int t   = row & (TT - 1);
    float c = cs[t * 64 + f];
    float s = sn[t * 64 + f];
    float2 v = *(float2*)(buf + ((size_t)idx << 1));
    float re = v.x, im = v.y;
    v.x = re * c - im * s;
    v.y = re * s + im * c;
    *(float2*)(buf + ((size_t)idx << 1)) = v;
}

// ---------------------------------------------------------------------------
// Flash attention (fp32, causal, MQA): BM=BN=64, D=128, 256 threads.
// Q/K in smem d-major (stride 68, float4 compute reads), V row-major (132),
// P staged in smem (stride 68). grid = (T/64, H, B).
// ---------------------------------------------------------------------------
#define ATTN_SMEM_FLOATS (128 * 68 * 2 + 64 * 132 + 64 * 68)
#define ATTN_SMEM_BYTES (ATTN_SMEM_FLOATS * 4)

__global__ __launch_bounds__(256) void attn_kernel(
    const float* __restrict__ Q, const float* __restrict__ K,
    const float* __restrict__ V, float* __restrict__ O)
{
    extern __shared__ float smn[];
    float* Qs = smn;                 // [d][r]  stride 68
    float* Ks = Qs + 128 * 68;       // [d][c]  stride 68
    float* Vs = Ks + 128 * 68;       // [c][d]  stride 132
    float* Ps = Vs + 64 * 132;       // [r][c]  stride 68

    const int tid = threadIdx.x;
    const int it  = blockIdx.x;
    const int h   = blockIdx.y;
    const int b   = blockIdx.z;
    const int i0  = it * 64;
    const int ty  = tid >> 4;   // row group: rows 4*ty..4*ty+3
    const int tx  = tid & 15;   // S: key cols 4*tx..; O: d cols 4*tx / 64+4*tx
    const float sm_scale = 0.08838834764831845f;   // 1/sqrt(128)

    // Load Q tile (pre-scaled). Writes: bank = (68d + r) % 32 -> conflict-free.
    {
        const float* qbase = Q + ((size_t)(b * TT + i0)) * CC + h * DD;
        for (int k = tid; k < 64 * 128; k += 256) {
            int d = k & 127, r = k >> 7;
            Qs[d * 68 + r] = qbase[(size_t)r * CC + d] * sm_scale;
        }
    }

    float m_prev[4], l[4], o[4][8];
#pragma unroll
    for (int i = 0; i < 4; i++) {
        m_prev[i] = -1e30f;
        l[i] = 0.f;
#pragma unroll
        for (int j = 0; j < 8; j++) o[i][j] = 0.f;
    }

    for (int jt = 0; jt <= it; jt++) {
        const int j0 = jt * 64;
        __syncthreads();   // prior PV-GEMM done reading Vs/Ps
        {
            const float* kbase = K + ((size_t)(b * TT + j0)) * DD;
            const float* vbase = V + ((size_t)(b * TT + j0)) * DD;
            for (int k = tid; k < 64 * 128; k += 256) {
                int d = k & 127, c = k >> 7;
                Ks[d * 68 + c] = kbase[(size_t)c * DD + d];
            }
            for (int k4 = tid; k4 < 64 * 32; k4 += 256) {
                int d4 = k4 & 31, c = k4 >> 5;
                *(float4*)&Vs[c * 132 + 4 * d4] =
                    *(const float4*)(vbase + (size_t)c * DD + 4 * d4);
            }
        }
        __syncthreads();

        // S = Q K^T (4x4 per thread)
        float s_[4][4];
#pragma unroll
        for (int i = 0; i < 4; i++)
#pragma unroll
            for (int j = 0; j < 4; j++) s_[i][j] = 0.f;

#pragma unroll 4
        for (int d = 0; d < 128; d++) {
            float4 qv = *(float4*)&Qs[d * 68 + 4 * ty];
            float4 kv = *(float4*)&Ks[d * 68 + 4 * tx];
            float qa[4] = {qv.x, qv.y, qv.z, qv.w};
            float ka[4] = {kv.x, kv.y, kv.z, kv.w};
#pragma unroll
            for (int i = 0; i < 4; i++)
#pragma unroll
                for (int j = 0; j < 4; j++)
                    s_[i][j] += qa[i] * ka[j];
        }

        if (jt == it) {   // diagonal tile: mask col > row (i0 == j0)
#pragma unroll
            for (int i = 0; i < 4; i++)
#pragma unroll
                for (int j = 0; j < 4; j++)
                    if (4 * tx + j > 4 * ty + i) s_[i][j] = -1e30f;
        }

        // Online softmax: row stats reduced across the 16 lanes of a ty-group
        float scl[4];
#pragma unroll
        for (int i = 0; i < 4; i++) {
            float mloc = fmaxf(fmaxf(s_[i][0], s_[i][1]), fmaxf(s_[i][2], s_[i][3]));
#pragma unroll
            for (int off = 8; off > 0; off >>= 1)
                mloc = fmaxf(mloc, __shfl_xor_sync(0xffffffffu, mloc, off));
            float m_new = fmaxf(m_prev[i], mloc);
            float p0 = __expf(s_[i][0] - m_new);
            float p1 = __expf(s_[i][1] - m_new);
            float p2 = __expf(s_[i][2] - m_new);
            float p3 = __expf(s_[i][3] - m_new);
            float ls = p0 + p1 + p2 + p3;
#pragma unroll
            for (int off = 8; off > 0; off >>= 1)
                ls += __shfl_xor_sync(0xffffffffu, ls, off);
            scl[i] = __expf(m_prev[i] - m_new);
            l[i] = l[i] * scl[i] + ls;
            m_prev[i] = m_new;
            *(float4*)&Ps[(4 * ty + i) * 68 + 4 * tx] = make_float4(p0, p1, p2, p3);
        }
        __syncthreads();   // Ps visible to all

        // O = O*scale + P @ V  (rows 4*ty+i, cols 4*tx+{0..3} and 64+4*tx+{0..3})
#pragma unroll
        for (int i = 0; i < 4; i++)
#pragma unroll
            for (int j = 0; j < 8; j++) o[i][j] *= scl[i];

#pragma unroll 2
        for (int c = 0; c < 64; c++) {
            float4 v0 = *(float4*)&Vs[c * 132 + 4 * tx];
            float4 v1 = *(float4*)&Vs[c * 132 + 64 + 4 * tx];
#pragma unroll
            for (int i = 0; i < 4; i++) {
                float p = Ps[(4 * ty + i) * 68 + c];
                o[i][0] += p * v0.x; o[i][1] += p * v0.y;
                o[i][2] += p * v0.z; o[i][3] += p * v0.w;
                o[i][4] += p * v1.x; o[i][5] += p * v1.y;
                o[i][6] += p * v1.z; o[i][7] += p * v1.w;
            }
        }
    }

    // Normalize + store
    float* obase = O + ((size_t)(b * TT + i0)) * CC + h * DD;
#pragma unroll
    for (int i = 0; i < 4; i++) {
        float inv = 1.f / l[i];
        size_t r = (size_t)(4 * ty + i);
        float4 r0 = make_float4(o[i][0] * inv, o[i][1] * inv, o[i][2] * inv, o[i][3] * inv);
        float4 r1 = make_float4(o[i][4] * inv, o[i][5] * inv, o[i][6] * inv, o[i][7] * inv);
        *(float4*)(obase + r * CC + 4 * tx)      = r0;
        *(float4*)(obase + r * CC + 64 + 4 * tx) = r1;
    }
}

// ---------------------------------------------------------------------------
// Launcher. Input order: x, cos, sin, mask, wq,wqb, wk,wkb, wv,wvb, wo,wob.
// Mask input unused (causal handled analytically; exp underflow identical).
// ---------------------------------------------------------------------------
extern "C" void kernel_launch(void* const* d_in, const int* in_sizes, int n_in,
                              void* d_out, int out_size)
{
    const float* x    = (const float*)d_in[0];
    const float* fcos = (const float*)d_in[1];
    const float* fsin = (const float*)d_in[2];
    const float* wq   = (const float*)d_in[4];
    const float* wqb  = (const float*)d_in[5];
    const float* wk   = (const float*)d_in[6];
    const float* wkb  = (const float*)d_in[7];
    const float* wv   = (const float*)d_in[8];
    const float* wvb  = (const float*)d_in[9];
    const float* wo   = (const float*)d_in[10];
    const float* wob  = (const float*)d_in[11];
    float* out = (float*)d_out;

    float *Qp, *Kp, *Vp, *Op;
    cudaGetSymbolAddress((void**)&Qp, g_Q);
    cudaGetSymbolAddress((void**)&Kp, g_K);
    cudaGetSymbolAddress((void**)&Vp, g_V);
    cudaGetSymbolAddress((void**)&Op, g_O);

    // QKV projections
    gemm_bias_kernel<<<dim3(CC / 128, MTOT / 128), 256>>>(x, wq, wqb, Qp, MTOT, CC, CC);
    gemm_bias_kernel<<<dim3(1, MTOT / 128), 256>>>(x, wk, wkb, Kp, MTOT, DD, CC);
    gemm_bias_kernel<<<dim3(1, MTOT / 128), 256>>>(x, wv, wvb, Vp, MTOT, DD, CC);

    // RoPE
    rope_kernel<<<(MTOT * (CC / 2)) / 256, 256>>>(Qp, fcos, fsin, 10);
    rope_kernel<<<(MTOT * (DD / 2)) / 256, 256>>>(Kp, fcos, fsin, 6);

    // Flash attention
    cudaFuncSetAttribute(attn_kernel, cudaFuncAttributeMaxDynamicSharedMemorySize,
                         ATTN_SMEM_BYTES);
    attn_kernel<<<dim3(TT / 64, HH, BB), 256, ATTN_SMEM_BYTES>>>(Qp, Kp, Vp, Op);

    // Output projection -> d_out
    gemm_bias_kernel<<<dim3(CC / 128, MTOT / 128), 256>>>(Op, wo, wob, out, MTOT, CC, CC);
}

// round 3
// speedup vs baseline: 1.4588x; 1.4588x over previous
#include <cuda_runtime.h>
#include <cuda_bf16.h>
#include <cstdint>

#define BB 2
#define TT 2048
#define CC 2048
#define HH 16
#define DD 128
#define MTOT (BB * TT)   // 4096
#define KTOT CC          // all GEMMs have K = 2048

typedef unsigned long long u64t;

// Scratch (allocation-free: __device__ globals)
__device__ float g_Q[(size_t)MTOT * CC];  // 32 MB
__device__ float g_K[(size_t)MTOT * DD];  //  2 MB
__device__ float g_V[(size_t)MTOT * DD];  //  2 MB
__device__ float g_O[(size_t)MTOT * CC];  // 32 MB

// ---------------------------------------------------------------------------
// PTX helpers (mma.sync / ldmatrix / f32x2) — base sm_103 features only
// ---------------------------------------------------------------------------
__device__ __forceinline__ uint32_t smem_u32(const void* p) {
    uint32_t a;
    asm("{ .reg .u64 t; cvta.to.shared.u64 t, %1; cvt.u32.u64 %0, t; }"
        : "=r"(a) : "l"(p));
    return a;
}

#define LDSM_X4(r0, r1, r2, r3, addr) \
    asm volatile("ldmatrix.sync.aligned.m8n8.x4.shared.b16 {%0,%1,%2,%3}, [%4];" \
                 : "=r"(r0), "=r"(r1), "=r"(r2), "=r"(r3) : "r"(addr))
#define LDSM_X4_T(r0, r1, r2, r3, addr) \
    asm volatile("ldmatrix.sync.aligned.m8n8.x4.trans.shared.b16 {%0,%1,%2,%3}, [%4];" \
                 : "=r"(r0), "=r"(r1), "=r"(r2), "=r"(r3) : "r"(addr))

#define MMA_BF16(d, a, b0v, b1v) \
    asm volatile("mma.sync.aligned.m16n8k16.row.col.f32.bf16.bf16.f32 " \
                 "{%0,%1,%2,%3}, {%4,%5,%6,%7}, {%8,%9}, {%0,%1,%2,%3};" \
                 : "+f"((d)[0]), "+f"((d)[1]), "+f"((d)[2]), "+f"((d)[3]) \
                 : "r"((a)[0]), "r"((a)[1]), "r"((a)[2]), "r"((a)[3]), \
                   "r"(b0v), "r"(b1v))

// f32x2 packed math
#define FMA2(d, a, b, c) asm("fma.rn.f32x2 %0, %1, %2, %3;" : "=l"(d) : "l"(a), "l"(b), "l"(c))
#define MUL2(d, a, b)    asm("mul.rn.f32x2 %0, %1, %2;"     : "=l"(d) : "l"(a), "l"(b))
#define PACK2(d, x)      asm("mov.b64 %0, {%1, %1};"        : "=l"(d) : "f"(x))
#define UNPK2(x, y, d)   asm("mov.b64 {%0, %1}, %2;"        : "=f"(x), "=f"(y) : "l"(d))

// ---------------------------------------------------------------------------
// mma.sync GEMM: Out[M,N] = A[M,2048] @ W[2048,N] + bias
// BM=128, BN=128, BK=32, 256 thr (8 warps = 4m x 2n; warp tile 32x64).
// bf16 hi/lo split (3 mma terms), fp32 accum. Double-buffered smem.
// SMEM stage: Ah[128][32] Al Bh[32][128] Bl (bf16), 16B-chunk XOR swizzle.
// ---------------------------------------------------------------------------
#define STG_BYTES 32768
#define GSMEM_BYTES (2 * STG_BYTES)

__device__ __forceinline__ uint32_t a_off(int r, int c) {
    return (uint32_t)(r * 64 + ((c ^ ((r >> 1) & 3)) << 4));
}
__device__ __forceinline__ uint32_t b_off(int r, int c) {
    return (uint32_t)(r * 256 + ((c ^ (r & 7)) << 4));
}

__device__ __forceinline__ void cvt8(float4 v0, float4 v1, uint4& hi, uint4& lo) {
    float f[8] = {v0.x, v0.y, v0.z, v0.w, v1.x, v1.y, v1.z, v1.w};
    uint32_t h[8], l[8];
#pragma unroll
    for (int i = 0; i < 8; i++) {
        __nv_bfloat16 hb = __float2bfloat16(f[i]);
        h[i] = (uint32_t)__bfloat16_as_ushort(hb);
        l[i] = (uint32_t)__bfloat16_as_ushort(
            __float2bfloat16(f[i] - __bfloat162float(hb)));
    }
    hi = make_uint4(h[0] | (h[1] << 16), h[2] | (h[3] << 16),
                    h[4] | (h[5] << 16), h[6] | (h[7] << 16));
    lo = make_uint4(l[0] | (l[1] << 16), l[2] | (l[3] << 16),
                    l[4] | (l[5] << 16), l[6] | (l[7] << 16));
}

// load+convert one BK=32 tile into smem stage (Ah|Al|Bh|Bl)
__device__ __forceinline__ void g2s(char* stg, const float* __restrict__ A,
                                    const float* __restrict__ W, int N,
                                    int m0, int n0, int k0, int tid) {
    // A tile: 128 rows x 32 k; 512 chunks of 8 floats -> 2 per thread
#pragma unroll
    for (int p = 0; p < 2; p++) {
        int cid = p * 256 + tid;
        int r = cid >> 2, c = cid & 3;
        const float* src = A + (size_t)(m0 + r) * KTOT + k0 + c * 8;
        float4 v0 = *(const float4*)src;
        float4 v1 = *(const float4*)(src + 4);
        uint4 hi, lo;
        cvt8(v0, v1, hi, lo);
        uint32_t off = a_off(r, c);
        *(uint4*)(stg + off) = hi;
        *(uint4*)(stg + 8192 + off) = lo;
    }
    // B tile: 32 k rows x 128 n; 512 chunks -> 2 per thread
#pragma unroll
    for (int p = 0; p < 2; p++) {
        int cid = p * 256 + tid;
        int r = cid >> 4, c = cid & 15;
        const float* src = W + (size_t)(k0 + r) * N + n0 + c * 8;
        float4 v0 = *(const float4*)src;
        float4 v1 = *(const float4*)(src + 4);
        uint4 hi, lo;
        cvt8(v0, v1, hi, lo);
        uint32_t off = b_off(r, c);
        *(uint4*)(stg + 16384 + off) = hi;
        *(uint4*)(stg + 24576 + off) = lo;
    }
}

__global__ __launch_bounds__(256)
void gemm_mma(const float* __restrict__ A, const float* __restrict__ W,
              const float* __restrict__ bias, float* __restrict__ Out, int N)
{
    extern __shared__ char sm[];
    const uint32_t sb = smem_u32(sm);
    const int tid  = threadIdx.x;
    const int lane = tid & 31;
    const int wid  = tid >> 5;
    const int wm   = wid >> 1;      // 0..3 -> m offset 32*wm
    const int wn   = wid & 1;       // 0..1 -> n offset 64*wn
    const int m0   = blockIdx.y * 128;
    const int n0   = blockIdx.x * 128;

    float acc[2][8][4];
#pragma unroll
    for (int i = 0; i < 2; i++)
#pragma unroll
        for (int j = 0; j < 8; j++)
#pragma unroll
            for (int q = 0; q < 4; q++) acc[i][j][q] = 0.f;

    // ldmatrix lane-address components
    const int lrow = ((lane >> 3) & 1) * 8 + (lane & 7);  // row within 16
    const int lsel = lane >> 4;                            // chunk select

    g2s(sm, A, W, N, m0, n0, 0, tid);
    __syncthreads();

    const int NITER = KTOT / 32;
    for (int it = 0; it < NITER; it++) {
        if (it + 1 < NITER)
            g2s(sm + ((it + 1) & 1) * STG_BYTES, A, W, N, m0, n0, (it + 1) * 32, tid);

        const uint32_t stA = sb + (uint32_t)(it & 1) * STG_BYTES;
        const uint32_t stB = stA + 16384;

#pragma unroll
        for (int ks = 0; ks < 2; ks++) {
            uint32_t ah[2][4], al[2][4];
#pragma unroll
            for (int mf = 0; mf < 2; mf++) {
                int row = wm * 32 + mf * 16 + lrow;
                int chunk = ks * 2 + lsel;
                uint32_t addr = stA + a_off(row, chunk);
                LDSM_X4(ah[mf][0], ah[mf][1], ah[mf][2], ah[mf][3], addr);
                LDSM_X4(al[mf][0], al[mf][1], al[mf][2], al[mf][3], addr + 8192);
            }
#pragma unroll
            for (int nj = 0; nj < 4; nj++) {
                int brow = ks * 16 + lrow;
                int bchunk = wn * 8 + nj * 2 + lsel;
                uint32_t baddr = stB + b_off(brow, bchunk);
                uint32_t bh[4], bl[4];
                LDSM_X4_T(bh[0], bh[1], bh[2], bh[3], baddr);
                LDSM_X4_T(bl[0], bl[1], bl[2], bl[3], baddr + 8192);
#pragma unroll
                for (int mf = 0; mf < 2; mf++) {
                    MMA_BF16(acc[mf][2 * nj],     ah[mf], bh[0], bh[1]);
                    MMA_BF16(acc[mf][2 * nj],     ah[mf], bl[0], bl[1]);
                    MMA_BF16(acc[mf][2 * nj],     al[mf], bh[0], bh[1]);
                    MMA_BF16(acc[mf][2 * nj + 1], ah[mf], bh[2], bh[3]);
                    MMA_BF16(acc[mf][2 * nj + 1], ah[mf], bl[2], bl[3]);
                    MMA_BF16(acc[mf][2 * nj + 1], al[mf], bh[2], bh[3]);
                }
            }
        }
        __syncthreads();
    }

    // Epilogue: frag (g, 2t) layout -> float2 stores + bias
    const int g = lane >> 2, t = lane & 3;
#pragma unroll
    for (int mf = 0; mf < 2; mf++) {
        int row0 = m0 + wm * 32 + mf * 16 + g;
#pragma unroll
        for (int nt = 0; nt < 8; nt++) {
            int col = n0 + wn * 64 + nt * 8 + 2 * t;
            float2 bi = *(const float2*)(bias + col);
            float2 o0 = make_float2(acc[mf][nt][0] + bi.x, acc[mf][nt][1] + bi.y);
            float2 o1 = make_float2(acc[mf][nt][2] + bi.x, acc[mf][nt][3] + bi.y);
            *(float2*)(Out + (size_t)row0 * N + col)       = o0;
            *(float2*)(Out + (size_t)(row0 + 8) * N + col) = o1;
        }
    }
}

// ---------------------------------------------------------------------------
// RoPE
// ---------------------------------------------------------------------------
__global__ __launch_bounds__(256) void rope_kernel(
    float* __restrict__ buf, const float* __restrict__ cs,
    const float* __restrict__ sn, int log2pairs)
{
    int idx = blockIdx.x * blockDim.x + threadIdx.x;
    int row = idx >> log2pairs;
    int p   = idx & ((1 << log2pairs) - 1);
    int f   = p & 63;
    int t   = row & (TT - 1);
    float c = cs[t * 64 + f];
    float s = sn[t * 64 + f];
    float2 v = *(float2*)(buf + ((size_t)idx << 1));
    float re = v.x, im = v.y;
    v.x = re * c - im * s;
    v.y = re * s + im * c;
    *(float2*)(buf + ((size_t)idx << 1)) = v;
}

// ---------------------------------------------------------------------------
// Flash attention, fp32 with packed f32x2 FMA: BM=BN=64, D=128, 256 thr.
// ---------------------------------------------------------------------------
#define ATTN_SMEM_FLOATS (128 * 68 * 2 + 64 * 132 + 64 * 68)
#define ATTN_SMEM_BYTES (ATTN_SMEM_FLOATS * 4)

__global__ __launch_bounds__(256) void attn_kernel(
    const float* __restrict__ Q, const float* __restrict__ K,
    const float* __restrict__ V, float* __restrict__ O)
{
    extern __shared__ float smn[];
    float* Qs = smn;                 // [d][r]  stride 68
    float* Ks = Qs + 128 * 68;       // [d][c]  stride 68
    float* Vs = Ks + 128 * 68;       // [c][d]  stride 132
    float* Ps = Vs + 64 * 132;       // [r][c]  stride 68

    const int tid = threadIdx.x;
    const int it  = blockIdx.x;
    const int h   = blockIdx.y;
    const int b   = blockIdx.z;
    const int i0  = it * 64;
    const int ty  = tid >> 4;
    const int tx  = tid & 15;
    const float sm_scale = 0.08838834764831845f;   // 1/sqrt(128)

    {
        const float* qbase = Q + ((size_t)(b * TT + i0)) * CC + h * DD;
        for (int k = tid; k < 64 * 128; k += 256) {
            int d = k & 127, r = k >> 7;
            Qs[d * 68 + r] = qbase[(size_t)r * CC + d] * sm_scale;
        }
    }

    float m_prev[4], l[4];
    u64t o2[4][4];
#pragma unroll
    for (int i = 0; i < 4; i++) {
        m_prev[i] = -1e30f;
        l[i] = 0.f;
#pragma unroll
        for (int j = 0; j < 4; j++) o2[i][j] = 0ULL;
    }

    for (int jt = 0; jt <= it; jt++) {
        const int j0 = jt * 64;
        __syncthreads();
        {
            const float* kbase = K + ((size_t)(b * TT + j0)) * DD;
            const float* vbase = V + ((size_t)(b * TT + j0)) * DD;
            for (int k = tid; k < 64 * 128; k += 256) {
                int d = k & 127, c = k >> 7;
                Ks[d * 68 + c] = kbase[(size_t)c * DD + d];
            }
            for (int k4 = tid; k4 < 64 * 32; k4 += 256) {
                int d4 = k4 & 31, c = k4 >> 5;
                *(float4*)&Vs[c * 132 + 4 * d4] =
                    *(const float4*)(vbase + (size_t)c * DD + 4 * d4);
            }
        }
        __syncthreads();

        // S = Q K^T (4x4 per thread, packed f32x2)
        u64t s2[4][2];
#pragma unroll
        for (int i = 0; i < 4; i++) { s2[i][0] = 0ULL; s2[i][1] = 0ULL; }

#pragma unroll 4
        for (int d = 0; d < 128; d++) {
            float4 qv = *(float4*)&Qs[d * 68 + 4 * ty];
            ulonglong2 kv = *(ulonglong2*)&Ks[d * 68 + 4 * tx];
            u64t qq;
            PACK2(qq, qv.x);
            FMA2(s2[0][0], qq, kv.x, s2[0][0]); FMA2(s2[0][1], qq, kv.y, s2[0][1]);
            PACK2(qq, qv.y);
            FMA2(s2[1][0], qq, kv.x, s2[1][0]); FMA2(s2[1][1], qq, kv.y, s2[1][1]);
            PACK2(qq, qv.z);
            FMA2(s2[2][0], qq, kv.x, s2[2][0]); FMA2(s2[2][1], qq, kv.y, s2[2][1]);
            PACK2(qq, qv.w);
            FMA2(s2[3][0], qq, kv.x, s2[3][0]); FMA2(s2[3][1], qq, kv.y, s2[3][1]);
        }

        float s_[4][4];
#pragma unroll
        for (int i = 0; i < 4; i++) {
            UNPK2(s_[i][0], s_[i][1], s2[i][0]);
            UNPK2(s_[i][2], s_[i][3], s2[i][1]);
        }

        if (jt == it) {
#pragma unroll
            for (int i = 0; i < 4; i++)
#pragma unroll
                for (int j = 0; j < 4; j++)
                    if (4 * tx + j > 4 * ty + i) s_[i][j] = -1e30f;
        }

        float scl[4];
#pragma unroll
        for (int i = 0; i < 4; i++) {
            float mloc = fmaxf(fmaxf(s_[i][0], s_[i][1]), fmaxf(s_[i][2], s_[i][3]));
#pragma unroll
            for (int off = 8; off > 0; off >>= 1)
                mloc = fmaxf(mloc, __shfl_xor_sync(0xffffffffu, mloc, off));
            float m_new = fmaxf(m_prev[i], mloc);
            float p0 = __expf(s_[i][0] - m_new);
            float p1 = __expf(s_[i][1] - m_new);
            float p2 = __expf(s_[i][2] - m_new);
            float p3 = __expf(s_[i][3] - m_new);
            float ls = p0 + p1 + p2 + p3;
#pragma unroll
            for (int off = 8; off > 0; off >>= 1)
                ls += __shfl_xor_sync(0xffffffffu, ls, off);
            scl[i] = __expf(m_prev[i] - m_new);
            l[i] = l[i] * scl[i] + ls;
            m_prev[i] = m_new;
            *(float4*)&Ps[(4 * ty + i) * 68 + 4 * tx] = make_float4(p0, p1, p2, p3);
        }
        __syncthreads();

        // O = O*scale + P @ V  (packed f32x2)
#pragma unroll
        for (int i = 0; i < 4; i++) {
            u64t scl2;
            PACK2(scl2, scl[i]);
            MUL2(o2[i][0], o2[i][0], scl2);
            MUL2(o2[i][1], o2[i][1], scl2);
            MUL2(o2[i][2], o2[i][2], scl2);
            MUL2(o2[i][3], o2[i][3], scl2);
        }

#pragma unroll 2
        for (int c = 0; c < 64; c++) {
            ulonglong2 v0 = *(ulonglong2*)&Vs[c * 132 + 4 * tx];
            ulonglong2 v1 = *(ulonglong2*)&Vs[c * 132 + 64 + 4 * tx];
#pragma unroll
            for (int i = 0; i < 4; i++) {
                float p = Ps[(4 * ty + i) * 68 + c];
                u64t pp;
                PACK2(pp, p);
                FMA2(o2[i][0], pp, v0.x, o2[i][0]);
                FMA2(o2[i][1], pp, v0.y, o2[i][1]);
                FMA2(o2[i][2], pp, v1.x, o2[i][2]);
                FMA2(o2[i][3], pp, v1.y, o2[i][3]);
            }
        }
    }

    // Normalize + store
    float* obase = O + ((size_t)(b * TT + i0)) * CC + h * DD;
#pragma unroll
    for (int i = 0; i < 4; i++) {
        float inv = 1.f / l[i];
        float o[8];
        UNPK2(o[0], o[1], o2[i][0]);
        UNPK2(o[2], o[3], o2[i][1]);
        UNPK2(o[4], o[5], o2[i][2]);
        UNPK2(o[6], o[7], o2[i][3]);
        size_t r = (size_t)(4 * ty + i);
        float4 r0 = make_float4(o[0] * inv, o[1] * inv, o[2] * inv, o[3] * inv);
        float4 r1 = make_float4(o[4] * inv, o[5] * inv, o[6] * inv, o[7] * inv);
        *(float4*)(obase + r * CC + 4 * tx)      = r0;
        *(float4*)(obase + r * CC + 64 + 4 * tx) = r1;
    }
}

// ---------------------------------------------------------------------------
// Launcher
// ---------------------------------------------------------------------------
extern "C" void kernel_launch(void* const* d_in, const int* in_sizes, int n_in,
                              void* d_out, int out_size)
{
    const float* x    = (const float*)d_in[0];
    const float* fcos = (const float*)d_in[1];
    const float* fsin = (const float*)d_in[2];
    const float* wq   = (const float*)d_in[4];
    const float* wqb  = (const float*)d_in[5];
    const float* wk   = (const float*)d_in[6];
    const float* wkb  = (const float*)d_in[7];
    const float* wv   = (const float*)d_in[8];
    const float* wvb  = (const float*)d_in[9];
    const float* wo   = (const float*)d_in[10];
    const float* wob  = (const float*)d_in[11];
    float* out = (float*)d_out;

    float *Qp, *Kp, *Vp, *Op;
    cudaGetSymbolAddress((void**)&Qp, g_Q);
    cudaGetSymbolAddress((void**)&Kp, g_K);
    cudaGetSymbolAddress((void**)&Vp, g_V);
    cudaGetSymbolAddress((void**)&Op, g_O);

    cudaFuncSetAttribute(gemm_mma, cudaFuncAttributeMaxDynamicSharedMemorySize,
                         GSMEM_BYTES);
    cudaFuncSetAttribute(attn_kernel, cudaFuncAttributeMaxDynamicSharedMemorySize,
                         ATTN_SMEM_BYTES);

    // QKV projections (mma.sync bf16-split)
    gemm_mma<<<dim3(CC / 128, MTOT / 128), 256, GSMEM_BYTES>>>(x, wq, wqb, Qp, CC);
    gemm_mma<<<dim3(1, MTOT / 128), 256, GSMEM_BYTES>>>(x, wk, wkb, Kp, DD);
    gemm_mma<<<dim3(1, MTOT / 128), 256, GSMEM_BYTES>>>(x, wv, wvb, Vp, DD);

    // RoPE
    rope_kernel<<<(MTOT * (CC / 2)) / 256, 256>>>(Qp, fcos, fsin, 10);
    rope_kernel<<<(MTOT * (DD / 2)) / 256, 256>>>(Kp, fcos, fsin, 6);

    // Flash attention
    attn_kernel<<<dim3(TT / 64, HH, BB), 256, ATTN_SMEM_BYTES>>>(Qp, Kp, Vp, Op);

    // Output projection -> d_out
    gemm_mma<<<dim3(CC / 128, MTOT / 128), 256, GSMEM_BYTES>>>(Op, wo, wob, out, CC);
}

// round 4
// speedup vs baseline: 3.2914x; 2.2562x over previous
#include <cuda_runtime.h>
#include <cuda_bf16.h>
#include <cstdint>

#define BB 2
#define TT 2048
#define CC 2048
#define HH 16
#define DD 128
#define MTOT (BB * TT)   // 4096
#define KTOT CC          // all GEMMs have K = 2048

typedef __nv_bfloat16 bf16;

// ---------------------------------------------------------------------------
// Scratch (allocation-free: __device__ globals)
// ---------------------------------------------------------------------------
__device__ float g_Q[(size_t)MTOT * CC];        // fp32 Q proj out (pre-rope)
__device__ float g_K[(size_t)MTOT * DD];        // fp32 K proj out
__device__ float g_V[(size_t)MTOT * DD];        // fp32 V proj out

__device__ bf16 g_xh[(size_t)MTOT * CC],  g_xl[(size_t)MTOT * CC];
__device__ bf16 g_wqh[(size_t)CC * CC],   g_wql[(size_t)CC * CC];
__device__ bf16 g_wkh[(size_t)CC * DD],   g_wkl[(size_t)CC * DD];
__device__ bf16 g_wvh[(size_t)CC * DD],   g_wvl[(size_t)CC * DD];
__device__ bf16 g_woh[(size_t)CC * CC],   g_wol[(size_t)CC * CC];

__device__ bf16 g_Qh[(size_t)MTOT * CC],  g_Ql[(size_t)MTOT * CC];  // [B,H,T,D]
__device__ bf16 g_Kh[(size_t)MTOT * DD],  g_Kl[(size_t)MTOT * DD];  // [B,T,D]
__device__ bf16 g_Vh[(size_t)MTOT * DD],  g_Vl[(size_t)MTOT * DD];  // [B,T,D]
__device__ bf16 g_Oh[(size_t)MTOT * CC],  g_Ol[(size_t)MTOT * CC];  // [B,T,H*D]

// ---------------------------------------------------------------------------
// PTX helpers
// ---------------------------------------------------------------------------
__device__ __forceinline__ uint32_t smem_u32(const void* p) {
    uint32_t a;
    asm("{ .reg .u64 t; cvta.to.shared.u64 t, %1; cvt.u32.u64 %0, t; }"
        : "=r"(a) : "l"(p));
    return a;
}

#define LDSM_X4(r0, r1, r2, r3, addr) \
    asm volatile("ldmatrix.sync.aligned.m8n8.x4.shared.b16 {%0,%1,%2,%3}, [%4];" \
                 : "=r"(r0), "=r"(r1), "=r"(r2), "=r"(r3) : "r"(addr))
#define LDSM_X4_T(r0, r1, r2, r3, addr) \
    asm volatile("ldmatrix.sync.aligned.m8n8.x4.trans.shared.b16 {%0,%1,%2,%3}, [%4];" \
                 : "=r"(r0), "=r"(r1), "=r"(r2), "=r"(r3) : "r"(addr))

#define MMA_BF16(d, a, b0v, b1v) \
    asm volatile("mma.sync.aligned.m16n8k16.row.col.f32.bf16.bf16.f32 " \
                 "{%0,%1,%2,%3}, {%4,%5,%6,%7}, {%8,%9}, {%0,%1,%2,%3};" \
                 : "+f"((d)[0]), "+f"((d)[1]), "+f"((d)[2]), "+f"((d)[3]) \
                 : "r"((a)[0]), "r"((a)[1]), "r"((a)[2]), "r"((a)[3]), \
                   "r"(b0v), "r"(b1v))

#define CP16(dst, src) \
    asm volatile("cp.async.cg.shared.global [%0], [%1], 16;" :: "r"(dst), "l"(src))
#define CP_COMMIT() asm volatile("cp.async.commit_group;" ::: "memory")
#define CP_WAIT(n)  asm volatile("cp.async.wait_group %0;" :: "n"(n) : "memory")

__device__ __forceinline__ uint32_t pack_bf2(bf16 a, bf16 b) {
    return ((uint32_t)__bfloat16_as_ushort(b) << 16) | (uint32_t)__bfloat16_as_ushort(a);
}
__device__ __forceinline__ void split2(float x, float y, uint32_t& hi, uint32_t& lo) {
    bf16 hx = __float2bfloat16(x), hy = __float2bfloat16(y);
    hi = pack_bf2(hx, hy);
    lo = pack_bf2(__float2bfloat16(x - __bfloat162float(hx)),
                  __float2bfloat16(y - __bfloat162float(hy)));
}

// ---------------------------------------------------------------------------
// Elementwise fp32 -> (bf16 hi, bf16 lo). n4 = n/4.
// ---------------------------------------------------------------------------
__global__ __launch_bounds__(256) void split_kernel(
    const float* __restrict__ in, bf16* __restrict__ hi, bf16* __restrict__ lo, int n4)
{
    int i = blockIdx.x * 256 + threadIdx.x;
    if (i >= n4) return;
    float4 v = ((const float4*)in)[i];
    uint32_t h0, l0, h1, l1;
    split2(v.x, v.y, h0, l0);
    split2(v.z, v.w, h1, l1);
    ((uint2*)hi)[i] = make_uint2(h0, h1);
    ((uint2*)lo)[i] = make_uint2(l0, l1);
}

// ---------------------------------------------------------------------------
// RoPE + split for Q: fp32 [B*T][2048] -> bf16 hi/lo [B,H,T,D], scaled.
// ---------------------------------------------------------------------------
__global__ __launch_bounds__(256) void ropeQ_kernel(
    const float* __restrict__ q, const float* __restrict__ cs,
    const float* __restrict__ sn, bf16* __restrict__ qh, bf16* __restrict__ ql)
{
    const float sm_scale = 0.08838834764831845f;  // 1/sqrt(128)
    int idx = blockIdx.x * 256 + threadIdx.x;      // pair index
    int row = idx >> 10;           // 0..4095 (b*T + t)
    int p   = idx & 1023;          // pair within row
    int h   = p >> 6;
    int f   = p & 63;
    int t   = row & (TT - 1);
    int b   = row >> 11;
    float c = cs[t * 64 + f], s = sn[t * 64 + f];
    float2 v = *(const float2*)(q + (size_t)row * CC + 2 * p);
    float re = (v.x * c - v.y * s) * sm_scale;
    float im = (v.x * s + v.y * c) * sm_scale;
    uint32_t hi, lo;
    split2(re, im, hi, lo);
    size_t orow = ((size_t)(b * HH + h) * TT + t) * DD + 2 * f;
    *(uint32_t*)(qh + orow) = hi;
    *(uint32_t*)(ql + orow) = lo;
}

// RoPE + split for K: fp32 [B*T][128] -> bf16 hi/lo same layout.
__global__ __launch_bounds__(256) void ropeK_kernel(
    const float* __restrict__ k, const float* __restrict__ cs,
    const float* __restrict__ sn, bf16* __restrict__ kh, bf16* __restrict__ kl)
{
    int idx = blockIdx.x * 256 + threadIdx.x;
    int row = idx >> 6;
    int f   = idx & 63;
    int t   = row & (TT - 1);
    float c = cs[t * 64 + f], s = sn[t * 64 + f];
    float2 v = *(const float2*)(k + (size_t)row * DD + 2 * f);
    float re = v.x * c - v.y * s;
    float im = v.x * s + v.y * c;
    uint32_t hi, lo;
    split2(re, im, hi, lo);
    size_t orow = (size_t)row * DD + 2 * f;
    *(uint32_t*)(kh + orow) = hi;
    *(uint32_t*)(kl + orow) = lo;
}

// ---------------------------------------------------------------------------
// GEMM v2: Out[M,N] = (Ah+Al)[M,2048] @ (Wh+Wl)[2048,N] + bias (3-term bf16)
// BM=128 BN=128 BK=32, 256 thr, cp.async 3-stage pipeline.
// stage layout (32KB): Ah[128][32] | Al | Bh[32][128] | Bl
// ---------------------------------------------------------------------------
#define STG_BYTES 32768
#define G2SMEM (3 * STG_BYTES)
#define NITER (KTOT / 32)   // 64

__device__ __forceinline__ uint32_t a_off(int r, int c) {
    return (uint32_t)(r * 64 + ((c ^ ((r >> 1) & 3)) << 4));
}
__device__ __forceinline__ uint32_t b_off(int r, int c) {
    return (uint32_t)(r * 256 + ((c ^ (r & 7)) << 4));
}

__device__ __forceinline__ void g2s_issue(
    uint32_t stg, const bf16* __restrict__ Ah, const bf16* __restrict__ Al,
    const bf16* __restrict__ Wh, const bf16* __restrict__ Wl,
    int N, int m0, int n0, int k0, int tid)
{
#pragma unroll
    for (int p = 0; p < 2; p++) {
        int cid = p * 256 + tid;
        int r = cid >> 2, c = cid & 3;
        size_t gs = (size_t)(m0 + r) * KTOT + k0 + c * 8;
        uint32_t off = a_off(r, c);
        CP16(stg + off, Ah + gs);
        CP16(stg + 8192 + off, Al + gs);
    }
#pragma unroll
    for (int p = 0; p < 2; p++) {
        int cid = p * 256 + tid;
        int r = cid >> 4, c = cid & 15;
        size_t gs = (size_t)(k0 + r) * N + n0 + c * 8;
        uint32_t off = b_off(r, c);
        CP16(stg + 16384 + off, Wh + gs);
        CP16(stg + 24576 + off, Wl + gs);
    }
}

__global__ __launch_bounds__(256, 2)
void gemm_bf(const bf16* __restrict__ Ah, const bf16* __restrict__ Al,
             const bf16* __restrict__ Wh, const bf16* __restrict__ Wl,
             const float* __restrict__ bias, float* __restrict__ Out, int N)
{
    extern __shared__ char sm[];
    const uint32_t sb = smem_u32(sm);
    const int tid  = threadIdx.x;
    const int lane = tid & 31;
    const int wid  = tid >> 5;
    const int wm   = wid >> 1;
    const int wn   = wid & 1;
    const int m0   = blockIdx.y * 128;
    const int n0   = blockIdx.x * 128;

    float acc[2][8][4];
#pragma unroll
    for (int i = 0; i < 2; i++)
#pragma unroll
        for (int j = 0; j < 8; j++)
#pragma unroll
            for (int q = 0; q < 4; q++) acc[i][j][q] = 0.f;

    const int lrow = lane & 15;
    const int lsel = lane >> 4;

    g2s_issue(sb, Ah, Al, Wh, Wl, N, m0, n0, 0, tid);
    CP_COMMIT();
    g2s_issue(sb + STG_BYTES, Ah, Al, Wh, Wl, N, m0, n0, 32, tid);
    CP_COMMIT();

    for (int it = 0; it < NITER; it++) {
        if (it > 0) __syncthreads();
        if (it + 2 < NITER) {
            g2s_issue(sb + ((it + 2) % 3) * STG_BYTES, Ah, Al, Wh, Wl, N,
                      m0, n0, (it + 2) * 32, tid);
            CP_COMMIT();
            CP_WAIT(2);
        } else if (it + 2 == NITER) {
            CP_WAIT(1);
        } else {
            CP_WAIT(0);
        }
        __syncthreads();

        const uint32_t stA = sb + (uint32_t)(it % 3) * STG_BYTES;
        const uint32_t stB = stA + 16384;

#pragma unroll
        for (int ks = 0; ks < 2; ks++) {
            uint32_t ah[2][4], al[2][4];
#pragma unroll
            for (int mf = 0; mf < 2; mf++) {
                int row = wm * 32 + mf * 16 + lrow;
                int chunk = ks * 2 + lsel;
                uint32_t addr = stA + a_off(row, chunk);
                LDSM_X4(ah[mf][0], ah[mf][1], ah[mf][2], ah[mf][3], addr);
                LDSM_X4(al[mf][0], al[mf][1], al[mf][2], al[mf][3], addr + 8192);
            }
#pragma unroll
            for (int nj = 0; nj < 4; nj++) {
                int brow = ks * 16 + lrow;
                int bchunk = wn * 8 + nj * 2 + lsel;
                uint32_t baddr = stB + b_off(brow, bchunk);
                uint32_t bh[4], bl[4];
                LDSM_X4_T(bh[0], bh[1], bh[2], bh[3], baddr);
                LDSM_X4_T(bl[0], bl[1], bl[2], bl[3], baddr + 8192);
#pragma unroll
                for (int mf = 0; mf < 2; mf++) {
                    MMA_BF16(acc[mf][2 * nj],     ah[mf], bh[0], bh[1]);
                    MMA_BF16(acc[mf][2 * nj],     ah[mf], bl[0], bl[1]);
                    MMA_BF16(acc[mf][2 * nj],     al[mf], bh[0], bh[1]);
                    MMA_BF16(acc[mf][2 * nj + 1], ah[mf], bh[2], bh[3]);
                    MMA_BF16(acc[mf][2 * nj + 1], ah[mf], bl[2], bl[3]);
                    MMA_BF16(acc[mf][2 * nj + 1], al[mf], bh[2], bh[3]);
                }
            }
        }
    }

    const int g = lane >> 2, t = lane & 3;
#pragma unroll
    for (int mf = 0; mf < 2; mf++) {
        int row0 = m0 + wm * 32 + mf * 16 + g;
#pragma unroll
        for (int nt = 0; nt < 8; nt++) {
            int col = n0 + wn * 64 + nt * 8 + 2 * t;
            float2 bi = *(const float2*)(bias + col);
            float2 o0 = make_float2(acc[mf][nt][0] + bi.x, acc[mf][nt][1] + bi.y);
            float2 o1 = make_float2(acc[mf][nt][2] + bi.x, acc[mf][nt][3] + bi.y);
            *(float2*)(Out + (size_t)row0 * N + col)       = o0;
            *(float2*)(Out + (size_t)(row0 + 8) * N + col) = o1;
        }
    }
}

// ---------------------------------------------------------------------------
// Flash attention on mma.sync: BM=128 (8 warps x 16 rows), BN=64, D=128.
// Q/K hi/lo bf16 (3-term QK^T), P hi/lo x V hi/lo (3-term PV).
// smem: Qh(32K) Ql(32K) + 2 KV stages (Kh,Kl,Vh,Vl = 64K each).
// ---------------------------------------------------------------------------
#define AQ_H 0u
#define AQ_L 32768u
#define AKV(s) (65536u + (uint32_t)(s) * 65536u)
#define A_SMEM 196608

__device__ __forceinline__ uint32_t toff(int r, int c) {
    return (uint32_t)(r * 256 + ((c ^ (r & 7)) << 4));
}

__global__ __launch_bounds__(256, 1) void attn_mma(
    const bf16* __restrict__ Qh, const bf16* __restrict__ Ql,
    const bf16* __restrict__ Kh, const bf16* __restrict__ Kl,
    const bf16* __restrict__ Vh, const bf16* __restrict__ Vl,
    bf16* __restrict__ Oh, bf16* __restrict__ Ol)
{
    extern __shared__ char sm[];
    const uint32_t sb = smem_u32(sm);
    const int tid = threadIdx.x, lane = tid & 31, w = tid >> 5;
    const int bx = blockIdx.x, h = blockIdx.y, b = blockIdx.z;
    const int i0 = bx * 128;
    const int jtmax = 2 * bx + 1;

    const size_t qbase  = ((size_t)(b * HH + h) * TT + i0) * DD;
    const size_t kvbase = (size_t)b * TT * DD;

    // Q tile + KV stage 0 (group 0)
#pragma unroll
    for (int i = 0; i < 8; i++) {
        int cid = i * 256 + tid;
        int r = cid >> 4, c = cid & 15;
        size_t gs = qbase + (size_t)r * DD + c * 8;
        uint32_t off = toff(r, c);
        CP16(sb + AQ_H + off, Qh + gs);
        CP16(sb + AQ_L + off, Ql + gs);
    }
#pragma unroll
    for (int i = 0; i < 4; i++) {
        int cid = i * 256 + tid;
        int r = cid >> 4, c = cid & 15;
        size_t gs = kvbase + (size_t)r * DD + c * 8;
        uint32_t off = toff(r, c);
        CP16(sb + AKV(0) + off,          Kh + gs);
        CP16(sb + AKV(0) + 16384 + off,  Kl + gs);
        CP16(sb + AKV(0) + 32768 + off,  Vh + gs);
        CP16(sb + AKV(0) + 49152 + off,  Vl + gs);
    }
    CP_COMMIT();

    // fragment lane constants
    const int lrA = lane & 15;                       // A / trans-B row-in-16
    const int lsA = lane >> 4;                       // A / trans-B chunk sel
    const int lrB = (lane & 7) + ((lane >> 4) << 3); // non-trans B row
    const int csB = (lane >> 3) & 1;                 // non-trans B chunk sel
    const int g = lane >> 2, t = lane & 3;

    float oa[16][4];
#pragma unroll
    for (int i = 0; i < 16; i++)
#pragma unroll
        for (int j = 0; j < 4; j++) oa[i][j] = 0.f;
    float m0r = -1e30f, m1r = -1e30f, l0r = 0.f, l1r = 0.f;

    for (int jt = 0; jt <= jtmax; jt++) {
        if (jt > 0) __syncthreads();
        if (jt + 1 <= jtmax) {
            uint32_t stg = AKV((jt + 1) & 1);
#pragma unroll
            for (int i = 0; i < 4; i++) {
                int cid = i * 256 + tid;
                int r = cid >> 4, c = cid & 15;
                size_t gs = kvbase + (size_t)((jt + 1) * 64 + r) * DD + c * 8;
                uint32_t off = toff(r, c);
                CP16(sb + stg + off,          Kh + gs);
                CP16(sb + stg + 16384 + off,  Kl + gs);
                CP16(sb + stg + 32768 + off,  Vh + gs);
                CP16(sb + stg + 49152 + off,  Vl + gs);
            }
            CP_COMMIT();
            CP_WAIT(1);
        } else {
            CP_WAIT(0);
        }
        __syncthreads();

        // fully-masked tile for this warp? (only possible on jt == jtmax)
        if (64 * jt > i0 + 16 * w + 15) continue;

        const uint32_t kvs = sb + AKV(jt & 1);

        // ---- S = Q K^T ----
        float sa[8][4];
#pragma unroll
        for (int i = 0; i < 8; i++)
#pragma unroll
            for (int j = 0; j < 4; j++) sa[i][j] = 0.f;

#pragma unroll
        for (int ks = 0; ks < 8; ks++) {
            uint32_t ah[4], al[4];
            uint32_t qaddr = sb + AQ_H + toff(16 * w + lrA, 2 * ks + lsA);
            LDSM_X4(ah[0], ah[1], ah[2], ah[3], qaddr);
            LDSM_X4(al[0], al[1], al[2], al[3], qaddr + AQ_L - AQ_H);
#pragma unroll
            for (int np = 0; np < 4; np++) {
                uint32_t kaddr = kvs + toff(np * 16 + lrB, 2 * ks + csB);
                uint32_t bh[4], bl[4];
                LDSM_X4(bh[0], bh[1], bh[2], bh[3], kaddr);
                LDSM_X4(bl[0], bl[1], bl[2], bl[3], kaddr + 16384);
                MMA_BF16(sa[2 * np],     ah, bh[0], bh[1]);
                MMA_BF16(sa[2 * np],     ah, bl[0], bl[1]);
                MMA_BF16(sa[2 * np],     al, bh[0], bh[1]);
                MMA_BF16(sa[2 * np + 1], ah, bh[2], bh[3]);
                MMA_BF16(sa[2 * np + 1], ah, bl[2], bl[3]);
                MMA_BF16(sa[2 * np + 1], al, bh[2], bh[3]);
            }
        }

        // ---- causal mask ----
        if (64 * jt + 63 > i0 + 16 * w) {
            int r0g = i0 + 16 * w + g;
#pragma unroll
            for (int nf = 0; nf < 8; nf++) {
                int cg = 64 * jt + nf * 8 + 2 * t;
                if (cg     > r0g)     sa[nf][0] = -1e30f;
                if (cg + 1 > r0g)     sa[nf][1] = -1e30f;
                if (cg     > r0g + 8) sa[nf][2] = -1e30f;
                if (cg + 1 > r0g + 8) sa[nf][3] = -1e30f;
            }
        }

        // ---- online softmax (rows g, g+8; reduce across quad lanes) ----
        float mx0 = -1e30f, mx1 = -1e30f;
#pragma unroll
        for (int nf = 0; nf < 8; nf++) {
            mx0 = fmaxf(mx0, fmaxf(sa[nf][0], sa[nf][1]));
            mx1 = fmaxf(mx1, fmaxf(sa[nf][2], sa[nf][3]));
        }
        mx0 = fmaxf(mx0, __shfl_xor_sync(0xffffffffu, mx0, 1));
        mx0 = fmaxf(mx0, __shfl_xor_sync(0xffffffffu, mx0, 2));
        mx1 = fmaxf(mx1, __shfl_xor_sync(0xffffffffu, mx1, 1));
        mx1 = fmaxf(mx1, __shfl_xor_sync(0xffffffffu, mx1, 2));
        float mn0 = fmaxf(m0r, mx0), mn1 = fmaxf(m1r, mx1);

        float sum0 = 0.f, sum1 = 0.f;
#pragma unroll
        for (int nf = 0; nf < 8; nf++) {
            sa[nf][0] = __expf(sa[nf][0] - mn0);
            sa[nf][1] = __expf(sa[nf][1] - mn0);
            sa[nf][2] = __expf(sa[nf][2] - mn1);
            sa[nf][3] = __expf(sa[nf][3] - mn1);
            sum0 += sa[nf][0] + sa[nf][1];
            sum1 += sa[nf][2] + sa[nf][3];
        }
        sum0 += __shfl_xor_sync(0xffffffffu, sum0, 1);
        sum0 += __shfl_xor_sync(0xffffffffu, sum0, 2);
        sum1 += __shfl_xor_sync(0xffffffffu, sum1, 1);
        sum1 += __shfl_xor_sync(0xffffffffu, sum1, 2);

        float scl0 = __expf(m0r - mn0), scl1 = __expf(m1r - mn1);
        l0r = l0r * scl0 + sum0;
        l1r = l1r * scl1 + sum1;
        m0r = mn0; m1r = mn1;

#pragma unroll
        for (int nf = 0; nf < 16; nf++) {
            oa[nf][0] *= scl0; oa[nf][1] *= scl0;
            oa[nf][2] *= scl1; oa[nf][3] *= scl1;
        }

        // ---- O += P V ----
#pragma unroll
        for (int s = 0; s < 4; s++) {
            uint32_t aPh[4], aPl[4];
            split2(sa[2 * s][0],     sa[2 * s][1],     aPh[0], aPl[0]);
            split2(sa[2 * s][2],     sa[2 * s][3],     aPh[1], aPl[1]);
            split2(sa[2 * s + 1][0], sa[2 * s + 1][1], aPh[2], aPl[2]);
            split2(sa[2 * s + 1][2], sa[2 * s + 1][3], aPh[3], aPl[3]);
#pragma unroll
            for (int np = 0; np < 8; np++) {
                uint32_t vaddr = kvs + 32768 + toff(s * 16 + lrA, 2 * np + lsA);
                uint32_t bh[4], bl[4];
                LDSM_X4_T(bh[0], bh[1], bh[2], bh[3], vaddr);
                LDSM_X4_T(bl[0], bl[1], bl[2], bl[3], vaddr + 16384);
                MMA_BF16(oa[2 * np],     aPh, bh[0], bh[1]);
                MMA_BF16(oa[2 * np],     aPh, bl[0], bl[1]);
                MMA_BF16(oa[2 * np],     aPl, bh[0], bh[1]);
                MMA_BF16(oa[2 * np + 1], aPh, bh[2], bh[3]);
                MMA_BF16(oa[2 * np + 1], aPh, bl[2], bl[3]);
                MMA_BF16(oa[2 * np + 1], aPl, bh[2], bh[3]);
            }
        }
    }

    // ---- epilogue: normalize, split to bf16 hi/lo, store [B,T,H*D] ----
    float inv0 = 1.f / l0r, inv1 = 1.f / l1r;
    size_t or0 = (size_t)(b * TT + i0 + 16 * w + g) * CC + h * DD;
    size_t or1 = or0 + (size_t)8 * CC;
#pragma unroll
    for (int nf = 0; nf < 16; nf++) {
        int col = nf * 8 + 2 * t;
        uint32_t hi, lo;
        split2(oa[nf][0] * inv0, oa[nf][1] * inv0, hi, lo);
        *(uint32_t*)(Oh + or0 + col) = hi;
        *(uint32_t*)(Ol + or0 + col) = lo;
        split2(oa[nf][2] * inv1, oa[nf][3] * inv1, hi, lo);
        *(uint32_t*)(Oh + or1 + col) = hi;
        *(uint32_t*)(Ol + or1 + col) = lo;
    }
}

// ---------------------------------------------------------------------------
// Launcher
// ---------------------------------------------------------------------------
extern "C" void kernel_launch(void* const* d_in, const int* in_sizes, int n_in,
                              void* d_out, int out_size)
{
    const float* x    = (const float*)d_in[0];
    const float* fcos = (const float*)d_in[1];
    const float* fsin = (const float*)d_in[2];
    const float* wq   = (const float*)d_in[4];
    const float* wqb  = (const float*)d_in[5];
    const float* wk   = (const float*)d_in[6];
    const float* wkb  = (const float*)d_in[7];
    const float* wv   = (const float*)d_in[8];
    const float* wvb  = (const float*)d_in[9];
    const float* wo   = (const float*)d_in[10];
    const float* wob  = (const float*)d_in[11];
    float* out = (float*)d_out;

    float *Qp, *Kp, *Vp;
    bf16 *xh, *xl, *wqh, *wql, *wkh, *wkl, *wvh, *wvl, *woh, *wol;
    bf16 *Qhp, *Qlp, *Khp, *Klp, *Vhp, *Vlp, *Ohp, *Olp;
    cudaGetSymbolAddress((void**)&Qp, g_Q);
    cudaGetSymbolAddress((void**)&Kp, g_K);
    cudaGetSymbolAddress((void**)&Vp, g_V);
    cudaGetSymbolAddress((void**)&xh, g_xh);   cudaGetSymbolAddress((void**)&xl, g_xl);
    cudaGetSymbolAddress((void**)&wqh, g_wqh); cudaGetSymbolAddress((void**)&wql, g_wql);
    cudaGetSymbolAddress((void**)&wkh, g_wkh); cudaGetSymbolAddress((void**)&wkl, g_wkl);
    cudaGetSymbolAddress((void**)&wvh, g_wvh); cudaGetSymbolAddress((void**)&wvl, g_wvl);
    cudaGetSymbolAddress((void**)&woh, g_woh); cudaGetSymbolAddress((void**)&wol, g_wol);
    cudaGetSymbolAddress((void**)&Qhp, g_Qh);  cudaGetSymbolAddress((void**)&Qlp, g_Ql);
    cudaGetSymbolAddress((void**)&Khp, g_Kh);  cudaGetSymbolAddress((void**)&Klp, g_Kl);
    cudaGetSymbolAddress((void**)&Vhp, g_Vh);  cudaGetSymbolAddress((void**)&Vlp, g_Vl);
    cudaGetSymbolAddress((void**)&Ohp, g_Oh);  cudaGetSymbolAddress((void**)&Olp, g_Ol);

    cudaFuncSetAttribute(gemm_bf, cudaFuncAttributeMaxDynamicSharedMemorySize, G2SMEM);
    cudaFuncSetAttribute(attn_mma, cudaFuncAttributeMaxDynamicSharedMemorySize, A_SMEM);

    // 1. pre-split inputs and weights to bf16 hi/lo
    split_kernel<<<8192, 256>>>(x,  xh,  xl,  MTOT * CC / 4);
    split_kernel<<<4096, 256>>>(wq, wqh, wql, CC * CC / 4);
    split_kernel<<<256,  256>>>(wk, wkh, wkl, CC * DD / 4);
    split_kernel<<<256,  256>>>(wv, wvh, wvl, CC * DD / 4);
    split_kernel<<<4096, 256>>>(wo, woh, wol, CC * CC / 4);

    // 2. projections
    gemm_bf<<<dim3(CC / 128, MTOT / 128), 256, G2SMEM>>>(xh, xl, wqh, wql, wqb, Qp, CC);
    gemm_bf<<<dim3(1, MTOT / 128), 256, G2SMEM>>>(xh, xl, wkh, wkl, wkb, Kp, DD);
    gemm_bf<<<dim3(1, MTOT / 128), 256, G2SMEM>>>(xh, xl, wvh, wvl, wvb, Vp, DD);

    // 3. RoPE + split (Q permuted to [B,H,T,D]); V split
    ropeQ_kernel<<<16384, 256>>>(Qp, fcos, fsin, Qhp, Qlp);
    ropeK_kernel<<<1024, 256>>>(Kp, fcos, fsin, Khp, Klp);
    split_kernel<<<512, 256>>>(Vp, Vhp, Vlp, MTOT * DD / 4);

    // 4. flash attention (mma.sync), writes bf16 hi/lo O
    attn_mma<<<dim3(TT / 128, HH, BB), 256, A_SMEM>>>(Qhp, Qlp, Khp, Klp, Vhp, Vlp,
                                                      Ohp, Olp);

    // 5. output projection -> d_out
    gemm_bf<<<dim3(CC / 128, MTOT / 128), 256, G2SMEM>>>(Ohp, Olp, woh, wol, wob, out, CC);
}

// round 5
// speedup vs baseline: 3.5940x; 1.0919x over previous
#include <cuda_runtime.h>
#include <cuda_bf16.h>
#include <cstdint>

#define BB 2
#define TT 2048
#define CC 2048
#define HH 16
#define DD 128
#define MTOT (BB * TT)   // 4096
#define KTOT CC          // all GEMMs have K = 2048
#define SMSCALE 0.08838834764831845f   // 1/sqrt(128)

typedef __nv_bfloat16 bf16;

// ---------------------------------------------------------------------------
// Scratch (allocation-free: __device__ globals)
// ---------------------------------------------------------------------------
__device__ bf16 g_xh[(size_t)MTOT * CC],  g_xl[(size_t)MTOT * CC];
__device__ bf16 g_wqh[(size_t)CC * CC],   g_wql[(size_t)CC * CC];
__device__ bf16 g_wkh[(size_t)CC * DD],   g_wkl[(size_t)CC * DD];
__device__ bf16 g_wvh[(size_t)CC * DD],   g_wvl[(size_t)CC * DD];
__device__ bf16 g_woh[(size_t)CC * CC],   g_wol[(size_t)CC * CC];

__device__ bf16 g_Qh[(size_t)MTOT * CC],  g_Ql[(size_t)MTOT * CC];  // [B,H,T,D]
__device__ bf16 g_Kh[(size_t)MTOT * DD],  g_Kl[(size_t)MTOT * DD];  // [B,T,D]
__device__ bf16 g_Vh[(size_t)MTOT * DD],  g_Vl[(size_t)MTOT * DD];  // [B,T,D]
__device__ bf16 g_Oh[(size_t)MTOT * CC],  g_Ol[(size_t)MTOT * CC];  // [B,T,H*D]

// ---------------------------------------------------------------------------
// PTX helpers
// ---------------------------------------------------------------------------
__device__ __forceinline__ uint32_t smem_u32(const void* p) {
    uint32_t a;
    asm("{ .reg .u64 t; cvta.to.shared.u64 t, %1; cvt.u32.u64 %0, t; }"
        : "=r"(a) : "l"(p));
    return a;
}

#define LDSM_X4(r0, r1, r2, r3, addr) \
    asm volatile("ldmatrix.sync.aligned.m8n8.x4.shared.b16 {%0,%1,%2,%3}, [%4];" \
                 : "=r"(r0), "=r"(r1), "=r"(r2), "=r"(r3) : "r"(addr))
#define LDSM_X4_T(r0, r1, r2, r3, addr) \
    asm volatile("ldmatrix.sync.aligned.m8n8.x4.trans.shared.b16 {%0,%1,%2,%3}, [%4];" \
                 : "=r"(r0), "=r"(r1), "=r"(r2), "=r"(r3) : "r"(addr))

#define MMA_BF16(d, a, b0v, b1v) \
    asm volatile("mma.sync.aligned.m16n8k16.row.col.f32.bf16.bf16.f32 " \
                 "{%0,%1,%2,%3}, {%4,%5,%6,%7}, {%8,%9}, {%0,%1,%2,%3};" \
                 : "+f"((d)[0]), "+f"((d)[1]), "+f"((d)[2]), "+f"((d)[3]) \
                 : "r"((a)[0]), "r"((a)[1]), "r"((a)[2]), "r"((a)[3]), \
                   "r"(b0v), "r"(b1v))

#define CP16(dst, src) \
    asm volatile("cp.async.cg.shared.global [%0], [%1], 16;" :: "r"(dst), "l"(src))
#define CP_COMMIT() asm volatile("cp.async.commit_group;" ::: "memory")
#define CP_WAIT(n)  asm volatile("cp.async.wait_group %0;" :: "n"(n) : "memory")

__device__ __forceinline__ uint32_t pack_bf2(bf16 a, bf16 b) {
    return ((uint32_t)__bfloat16_as_ushort(b) << 16) | (uint32_t)__bfloat16_as_ushort(a);
}
__device__ __forceinline__ void split2(float x, float y, uint32_t& hi, uint32_t& lo) {
    bf16 hx = __float2bfloat16(x), hy = __float2bfloat16(y);
    hi = pack_bf2(hx, hy);
    lo = pack_bf2(__float2bfloat16(x - __bfloat162float(hx)),
                  __float2bfloat16(y - __bfloat162float(hy)));
}

// ---------------------------------------------------------------------------
// Elementwise fp32 -> (bf16 hi, bf16 lo). n4 = n/4.
// ---------------------------------------------------------------------------
__global__ __launch_bounds__(256) void split_kernel(
    const float* __restrict__ in, bf16* __restrict__ hi, bf16* __restrict__ lo, int n4)
{
    int i = blockIdx.x * 256 + threadIdx.x;
    if (i >= n4) return;
    float4 v = ((const float4*)in)[i];
    uint32_t h0, l0, h1, l1;
    split2(v.x, v.y, h0, l0);
    split2(v.z, v.w, h1, l1);
    ((uint2*)hi)[i] = make_uint2(h0, h1);
    ((uint2*)lo)[i] = make_uint2(l0, l1);
}

// ---------------------------------------------------------------------------
// GEMM: Out = (Ah+Al)[M,2048] @ (Wh+Wl)[2048,N] + bias (3-term bf16, fp32 acc)
// BM=128 BN=128 BK=32, 256 thr, cp.async 3-stage, ONE sync per iter.
// MODE 0: fp32 out.  MODE 1: RoPE+scale+split -> [B,H,T,D] hi/lo (Q).
// MODE 2: RoPE+split -> [B,T,D] hi/lo (K).  MODE 3: split -> hi/lo (V).
// ---------------------------------------------------------------------------
#define STG_BYTES 32768
#define G2SMEM (3 * STG_BYTES)
#define NITER (KTOT / 32)   // 64

__device__ __forceinline__ uint32_t a_off(int r, int c) {
    return (uint32_t)(r * 64 + ((c ^ ((r >> 1) & 3)) << 4));
}
__device__ __forceinline__ uint32_t b_off(int r, int c) {
    return (uint32_t)(r * 256 + ((c ^ (r & 7)) << 4));
}

__device__ __forceinline__ void g2s_issue(
    uint32_t stg, const bf16* __restrict__ Ah, const bf16* __restrict__ Al,
    const bf16* __restrict__ Wh, const bf16* __restrict__ Wl,
    int N, int m0, int n0, int k0, int tid)
{
#pragma unroll
    for (int p = 0; p < 2; p++) {
        int cid = p * 256 + tid;
        int r = cid >> 2, c = cid & 3;
        size_t gs = (size_t)(m0 + r) * KTOT + k0 + c * 8;
        uint32_t off = a_off(r, c);
        CP16(stg + off, Ah + gs);
        CP16(stg + 8192 + off, Al + gs);
    }
#pragma unroll
    for (int p = 0; p < 2; p++) {
        int cid = p * 256 + tid;
        int r = cid >> 4, c = cid & 15;
        size_t gs = (size_t)(k0 + r) * N + n0 + c * 8;
        uint32_t off = b_off(r, c);
        CP16(stg + 16384 + off, Wh + gs);
        CP16(stg + 24576 + off, Wl + gs);
    }
}

template <int MODE>
__global__ __launch_bounds__(256, 2)
void gemm_bf(const bf16* __restrict__ Ah, const bf16* __restrict__ Al,
             const bf16* __restrict__ Wh, const bf16* __restrict__ Wl,
             const float* __restrict__ bias, float* __restrict__ OutF,
             bf16* __restrict__ OutH, bf16* __restrict__ OutL,
             const float* __restrict__ cs, const float* __restrict__ sn, int N)
{
    extern __shared__ char sm[];
    const uint32_t sb = smem_u32(sm);
    const int tid  = threadIdx.x;
    const int lane = tid & 31;
    const int wid  = tid >> 5;
    const int wm   = wid >> 1;
    const int wn   = wid & 1;
    const int m0   = blockIdx.y * 128;
    const int n0   = blockIdx.x * 128;

    float acc[2][8][4];
#pragma unroll
    for (int i = 0; i < 2; i++)
#pragma unroll
        for (int j = 0; j < 8; j++)
#pragma unroll
            for (int q = 0; q < 4; q++) acc[i][j][q] = 0.f;

    const int lrow = lane & 15;
    const int lsel = lane >> 4;

    g2s_issue(sb, Ah, Al, Wh, Wl, N, m0, n0, 0, tid);
    CP_COMMIT();
    g2s_issue(sb + STG_BYTES, Ah, Al, Wh, Wl, N, m0, n0, 32, tid);
    CP_COMMIT();

    for (int it = 0; it < NITER; it++) {
        if (it == NITER - 1) CP_WAIT(0); else CP_WAIT(1);
        __syncthreads();
        if (it + 2 < NITER) {
            g2s_issue(sb + ((it + 2) % 3) * STG_BYTES, Ah, Al, Wh, Wl, N,
                      m0, n0, (it + 2) * 32, tid);
            CP_COMMIT();
        }

        const uint32_t stA = sb + (uint32_t)(it % 3) * STG_BYTES;
        const uint32_t stB = stA + 16384;

#pragma unroll
        for (int ks = 0; ks < 2; ks++) {
            uint32_t ah[2][4], al[2][4];
#pragma unroll
            for (int mf = 0; mf < 2; mf++) {
                int row = wm * 32 + mf * 16 + lrow;
                int chunk = ks * 2 + lsel;
                uint32_t addr = stA + a_off(row, chunk);
                LDSM_X4(ah[mf][0], ah[mf][1], ah[mf][2], ah[mf][3], addr);
                LDSM_X4(al[mf][0], al[mf][1], al[mf][2], al[mf][3], addr + 8192);
            }
#pragma unroll
            for (int nj = 0; nj < 4; nj++) {
                int brow = ks * 16 + lrow;
                int bchunk = wn * 8 + nj * 2 + lsel;
                uint32_t baddr = stB + b_off(brow, bchunk);
                uint32_t bh[4], bl[4];
                LDSM_X4_T(bh[0], bh[1], bh[2], bh[3], baddr);
                LDSM_X4_T(bl[0], bl[1], bl[2], bl[3], baddr + 8192);
#pragma unroll
                for (int mf = 0; mf < 2; mf++) {
                    MMA_BF16(acc[mf][2 * nj],     ah[mf], bh[0], bh[1]);
                    MMA_BF16(acc[mf][2 * nj],     ah[mf], bl[0], bl[1]);
                    MMA_BF16(acc[mf][2 * nj],     al[mf], bh[0], bh[1]);
                    MMA_BF16(acc[mf][2 * nj + 1], ah[mf], bh[2], bh[3]);
                    MMA_BF16(acc[mf][2 * nj + 1], ah[mf], bl[2], bl[3]);
                    MMA_BF16(acc[mf][2 * nj + 1], al[mf], bh[2], bh[3]);
                }
            }
        }
    }

    // ---- epilogue ----
    const int g = lane >> 2, t = lane & 3;
#pragma unroll
    for (int mf = 0; mf < 2; mf++) {
        int row0 = m0 + wm * 32 + mf * 16 + g;
#pragma unroll
        for (int nt = 0; nt < 8; nt++) {
            int col = n0 + wn * 64 + nt * 8 + 2 * t;
            float2 bi = *(const float2*)(bias + col);
            float a0 = acc[mf][nt][0] + bi.x, a1 = acc[mf][nt][1] + bi.y;
            float a2 = acc[mf][nt][2] + bi.x, a3 = acc[mf][nt][3] + bi.y;
            if (MODE == 0) {
                *(float2*)(OutF + (size_t)row0 * N + col)       = make_float2(a0, a1);
                *(float2*)(OutF + (size_t)(row0 + 8) * N + col) = make_float2(a2, a3);
            } else if (MODE == 3) {
                uint32_t hi, lo;
                split2(a0, a1, hi, lo);
                *(uint32_t*)(OutH + (size_t)row0 * N + col) = hi;
                *(uint32_t*)(OutL + (size_t)row0 * N + col) = lo;
                split2(a2, a3, hi, lo);
                *(uint32_t*)(OutH + (size_t)(row0 + 8) * N + col) = hi;
                *(uint32_t*)(OutL + (size_t)(row0 + 8) * N + col) = lo;
            } else {
                int f = (col & 127) >> 1;
#pragma unroll
                for (int rr = 0; rr < 2; rr++) {
                    int r = row0 + rr * 8;
                    int tloc = r & (TT - 1);
                    float c = cs[tloc * 64 + f], s = sn[tloc * 64 + f];
                    float re = rr ? a2 : a0, im = rr ? a3 : a1;
                    float ore = re * c - im * s;
                    float oim = re * s + im * c;
                    if (MODE == 1) { ore *= SMSCALE; oim *= SMSCALE; }
                    uint32_t hi, lo;
                    split2(ore, oim, hi, lo);
                    size_t idx;
                    if (MODE == 1) {
                        int bq = r >> 11, hq = col >> 7;
                        idx = ((size_t)(bq * HH + hq) * TT + tloc) * DD + (col & 127);
                    } else {
                        idx = (size_t)r * N + col;
                    }
                    *(uint32_t*)(OutH + idx) = hi;
                    *(uint32_t*)(OutL + idx) = lo;
                }
            }
        }
    }
}

// ---------------------------------------------------------------------------
// Flash attention on mma.sync: BM=128 (8 warps x 16 rows), BN=64, D=128.
// 1D grid, heaviest Q-tiles scheduled first.
// ---------------------------------------------------------------------------
#define AQ_H 0u
#define AQ_L 32768u
#define AKV(s) (65536u + (uint32_t)(s) * 65536u)
#define A_SMEM 196608

__device__ __forceinline__ uint32_t toff(int r, int c) {
    return (uint32_t)(r * 256 + ((c ^ (r & 7)) << 4));
}

__global__ __launch_bounds__(256, 1) void attn_mma(
    const bf16* __restrict__ Qh, const bf16* __restrict__ Ql,
    const bf16* __restrict__ Kh, const bf16* __restrict__ Kl,
    const bf16* __restrict__ Vh, const bf16* __restrict__ Vl,
    bf16* __restrict__ Oh, bf16* __restrict__ Ol)
{
    extern __shared__ char sm[];
    const uint32_t sb = smem_u32(sm);
    const int tid = threadIdx.x, lane = tid & 31, w = tid >> 5;
    // heavy-first CTA mapping: bx descending
    const int id = blockIdx.x;
    const int bx = (TT / 128 - 1) - (id >> 5);
    const int hb = id & 31;
    const int h  = hb & 15;
    const int b  = hb >> 4;
    const int i0 = bx * 128;
    const int jtmax = 2 * bx + 1;

    const size_t qbase  = ((size_t)(b * HH + h) * TT + i0) * DD;
    const size_t kvbase = (size_t)b * TT * DD;

    // Q tile + KV stage 0
#pragma unroll
    for (int i = 0; i < 8; i++) {
        int cid = i * 256 + tid;
        int r = cid >> 4, c = cid & 15;
        size_t gs = qbase + (size_t)r * DD + c * 8;
        uint32_t off = toff(r, c);
        CP16(sb + AQ_H + off, Qh + gs);
        CP16(sb + AQ_L + off, Ql + gs);
    }
#pragma unroll
    for (int i = 0; i < 4; i++) {
        int cid = i * 256 + tid;
        int r = cid >> 4, c = cid & 15;
        size_t gs = kvbase + (size_t)r * DD + c * 8;
        uint32_t off = toff(r, c);
        CP16(sb + AKV(0) + off,          Kh + gs);
        CP16(sb + AKV(0) + 16384 + off,  Kl + gs);
        CP16(sb + AKV(0) + 32768 + off,  Vh + gs);
        CP16(sb + AKV(0) + 49152 + off,  Vl + gs);
    }
    CP_COMMIT();

    const int lrA = lane & 15;
    const int lsA = lane >> 4;
    const int lrB = (lane & 7) + ((lane >> 4) << 3);
    const int csB = (lane >> 3) & 1;
    const int g = lane >> 2, t = lane & 3;

    float oa[16][4];
#pragma unroll
    for (int i = 0; i < 16; i++)
#pragma unroll
        for (int j = 0; j < 4; j++) oa[i][j] = 0.f;
    float m0r = -1e30f, m1r = -1e30f, l0r = 0.f, l1r = 0.f;

    for (int jt = 0; jt <= jtmax; jt++) {
        if (jt > 0) __syncthreads();
        if (jt + 1 <= jtmax) {
            uint32_t stg = AKV((jt + 1) & 1);
#pragma unroll
            for (int i = 0; i < 4; i++) {
                int cid = i * 256 + tid;
                int r = cid >> 4, c = cid & 15;
                size_t gs = kvbase + (size_t)((jt + 1) * 64 + r) * DD + c * 8;
                uint32_t off = toff(r, c);
                CP16(sb + stg + off,          Kh + gs);
                CP16(sb + stg + 16384 + off,  Kl + gs);
                CP16(sb + stg + 32768 + off,  Vh + gs);
                CP16(sb + stg + 49152 + off,  Vl + gs);
            }
            CP_COMMIT();
            CP_WAIT(1);
        } else {
            CP_WAIT(0);
        }
        __syncthreads();

        if (64 * jt > i0 + 16 * w + 15) continue;

        const uint32_t kvs = sb + AKV(jt & 1);

        // ---- S = Q K^T ----
        float sa[8][4];
#pragma unroll
        for (int i = 0; i < 8; i++)
#pragma unroll
            for (int j = 0; j < 4; j++) sa[i][j] = 0.f;

#pragma unroll
        for (int ks = 0; ks < 8; ks++) {
            uint32_t ah[4], al[4];
            uint32_t qaddr = sb + AQ_H + toff(16 * w + lrA, 2 * ks + lsA);
            LDSM_X4(ah[0], ah[1], ah[2], ah[3], qaddr);
            LDSM_X4(al[0], al[1], al[2], al[3], qaddr + AQ_L - AQ_H);
#pragma unroll
            for (int np = 0; np < 4; np++) {
                uint32_t kaddr = kvs + toff(np * 16 + lrB, 2 * ks + csB);
                uint32_t bh[4], bl[4];
                LDSM_X4(bh[0], bh[1], bh[2], bh[3], kaddr);
                LDSM_X4(bl[0], bl[1], bl[2], bl[3], kaddr + 16384);
                MMA_BF16(sa[2 * np],     ah, bh[0], bh[1]);
                MMA_BF16(sa[2 * np],     ah, bl[0], bl[1]);
                MMA_BF16(sa[2 * np],     al, bh[0], bh[1]);
                MMA_BF16(sa[2 * np + 1], ah, bh[2], bh[3]);
                MMA_BF16(sa[2 * np + 1], ah, bl[2], bl[3]);
                MMA_BF16(sa[2 * np + 1], al, bh[2], bh[3]);
            }
        }

        // ---- causal mask ----
        if (64 * jt + 63 > i0 + 16 * w) {
            int r0g = i0 + 16 * w + g;
#pragma unroll
            for (int nf = 0; nf < 8; nf++) {
                int cg = 64 * jt + nf * 8 + 2 * t;
                if (cg     > r0g)     sa[nf][0] = -1e30f;
                if (cg + 1 > r0g)     sa[nf][1] = -1e30f;
                if (cg     > r0g + 8) sa[nf][2] = -1e30f;
                if (cg + 1 > r0g + 8) sa[nf][3] = -1e30f;
            }
        }

        // ---- online softmax ----
        float mx0 = -1e30f, mx1 = -1e30f;
#pragma unroll
        for (int nf = 0; nf < 8; nf++) {
            mx0 = fmaxf(mx0, fmaxf(sa[nf][0], sa[nf][1]));
            mx1 = fmaxf(mx1, fmaxf(sa[nf][2], sa[nf][3]));
        }
        mx0 = fmaxf(mx0, __shfl_xor_sync(0xffffffffu, mx0, 1));
        mx0 = fmaxf(mx0, __shfl_xor_sync(0xffffffffu, mx0, 2));
        mx1 = fmaxf(mx1, __shfl_xor_sync(0xffffffffu, mx1, 1));
        mx1 = fmaxf(mx1, __shfl_xor_sync(0xffffffffu, mx1, 2));
        float mn0 = fmaxf(m0r, mx0), mn1 = fmaxf(m1r, mx1);

        float sum0 = 0.f, sum1 = 0.f;
#pragma unroll
        for (int nf = 0; nf < 8; nf++) {
            sa[nf][0] = __expf(sa[nf][0] - mn0);
            sa[nf][1] = __expf(sa[nf][1] - mn0);
            sa[nf][2] = __expf(sa[nf][2] - mn1);
            sa[nf][3] = __expf(sa[nf][3] - mn1);
            sum0 += sa[nf][0] + sa[nf][1];
            sum1 += sa[nf][2] + sa[nf][3];
        }
        sum0 += __shfl_xor_sync(0xffffffffu, sum0, 1);
        sum0 += __shfl_xor_sync(0xffffffffu, sum0, 2);
        sum1 += __shfl_xor_sync(0xffffffffu, sum1, 1);
        sum1 += __shfl_xor_sync(0xffffffffu, sum1, 2);

        float scl0 = __expf(m0r - mn0), scl1 = __expf(m1r - mn1);
        l0r = l0r * scl0 + sum0;
        l1r = l1r * scl1 + sum1;
        m0r = mn0; m1r = mn1;

#pragma unroll
        for (int nf = 0; nf < 16; nf++) {
            oa[nf][0] *= scl0; oa[nf][1] *= scl0;
            oa[nf][2] *= scl1; oa[nf][3] *= scl1;
        }

        // ---- O += P V ----
#pragma unroll
        for (int s = 0; s < 4; s++) {
            uint32_t aPh[4], aPl[4];
            split2(sa[2 * s][0],     sa[2 * s][1],     aPh[0], aPl[0]);
            split2(sa[2 * s][2],     sa[2 * s][3],     aPh[1], aPl[1]);
            split2(sa[2 * s + 1][0], sa[2 * s + 1][1], aPh[2], aPl[2]);
            split2(sa[2 * s + 1][2], sa[2 * s + 1][3], aPh[3], aPl[3]);
#pragma unroll
            for (int np = 0; np < 8; np++) {
                uint32_t vaddr = kvs + 32768 + toff(s * 16 + lrA, 2 * np + lsA);
                uint32_t bh[4], bl[4];
                LDSM_X4_T(bh[0], bh[1], bh[2], bh[3], vaddr);
                LDSM_X4_T(bl[0], bl[1], bl[2], bl[3], vaddr + 16384);
                MMA_BF16(oa[2 * np],     aPh, bh[0], bh[1]);
                MMA_BF16(oa[2 * np],     aPh, bl[0], bl[1]);
                MMA_BF16(oa[2 * np],     aPl, bh[0], bh[1]);
                MMA_BF16(oa[2 * np + 1], aPh, bh[2], bh[3]);
                MMA_BF16(oa[2 * np + 1], aPh, bl[2], bl[3]);
                MMA_BF16(oa[2 * np + 1], aPl, bh[2], bh[3]);
            }
        }
    }

    // ---- epilogue ----
    float inv0 = 1.f / l0r, inv1 = 1.f / l1r;
    size_t or0 = (size_t)(b * TT + i0 + 16 * w + g) * CC + h * DD;
    size_t or1 = or0 + (size_t)8 * CC;
#pragma unroll
    for (int nf = 0; nf < 16; nf++) {
        int col = nf * 8 + 2 * t;
        uint32_t hi, lo;
        split2(oa[nf][0] * inv0, oa[nf][1] * inv0, hi, lo);
        *(uint32_t*)(Oh + or0 + col) = hi;
        *(uint32_t*)(Ol + or0 + col) = lo;
        split2(oa[nf][2] * inv1, oa[nf][3] * inv1, hi, lo);
        *(uint32_t*)(Oh + or1 + col) = hi;
        *(uint32_t*)(Ol + or1 + col) = lo;
    }
}

// ---------------------------------------------------------------------------
// Launcher
// ---------------------------------------------------------------------------
extern "C" void kernel_launch(void* const* d_in, const int* in_sizes, int n_in,
                              void* d_out, int out_size)
{
    const float* x    = (const float*)d_in[0];
    const float* fcos = (const float*)d_in[1];
    const float* fsin = (const float*)d_in[2];
    const float* wq   = (const float*)d_in[4];
    const float* wqb  = (const float*)d_in[5];
    const float* wk   = (const float*)d_in[6];
    const float* wkb  = (const float*)d_in[7];
    const float* wv   = (const float*)d_in[8];
    const float* wvb  = (const float*)d_in[9];
    const float* wo   = (const float*)d_in[10];
    const float* wob  = (const float*)d_in[11];
    float* out = (float*)d_out;

    bf16 *xh, *xl, *wqh, *wql, *wkh, *wkl, *wvh, *wvl, *woh, *wol;
    bf16 *Qhp, *Qlp, *Khp, *Klp, *Vhp, *Vlp, *Ohp, *Olp;
    cudaGetSymbolAddress((void**)&xh, g_xh);   cudaGetSymbolAddress((void**)&xl, g_xl);
    cudaGetSymbolAddress((void**)&wqh, g_wqh); cudaGetSymbolAddress((void**)&wql, g_wql);
    cudaGetSymbolAddress((void**)&wkh, g_wkh); cudaGetSymbolAddress((void**)&wkl, g_wkl);
    cudaGetSymbolAddress((void**)&wvh, g_wvh); cudaGetSymbolAddress((void**)&wvl, g_wvl);
    cudaGetSymbolAddress((void**)&woh, g_woh); cudaGetSymbolAddress((void**)&wol, g_wol);
    cudaGetSymbolAddress((void**)&Qhp, g_Qh);  cudaGetSymbolAddress((void**)&Qlp, g_Ql);
    cudaGetSymbolAddress((void**)&Khp, g_Kh);  cudaGetSymbolAddress((void**)&Klp, g_Kl);
    cudaGetSymbolAddress((void**)&Vhp, g_Vh);  cudaGetSymbolAddress((void**)&Vlp, g_Vl);
    cudaGetSymbolAddress((void**)&Ohp, g_Oh);  cudaGetSymbolAddress((void**)&Olp, g_Ol);

    cudaFuncSetAttribute(gemm_bf<0>, cudaFuncAttributeMaxDynamicSharedMemorySize, G2SMEM);
    cudaFuncSetAttribute(gemm_bf<1>, cudaFuncAttributeMaxDynamicSharedMemorySize, G2SMEM);
    cudaFuncSetAttribute(gemm_bf<2>, cudaFuncAttributeMaxDynamicSharedMemorySize, G2SMEM);
    cudaFuncSetAttribute(gemm_bf<3>, cudaFuncAttributeMaxDynamicSharedMemorySize, G2SMEM);
    cudaFuncSetAttribute(attn_mma, cudaFuncAttributeMaxDynamicSharedMemorySize, A_SMEM);

    // 1. pre-split inputs and weights to bf16 hi/lo
    split_kernel<<<8192, 256>>>(x,  xh,  xl,  MTOT * CC / 4);
    split_kernel<<<4096, 256>>>(wq, wqh, wql, CC * CC / 4);
    split_kernel<<<256,  256>>>(wk, wkh, wkl, CC * DD / 4);
    split_kernel<<<256,  256>>>(wv, wvh, wvl, CC * DD / 4);
    split_kernel<<<4096, 256>>>(wo, woh, wol, CC * CC / 4);

    // 2. projections with fused RoPE/scale/split epilogues
    gemm_bf<1><<<dim3(CC / 128, MTOT / 128), 256, G2SMEM>>>(
        xh, xl, wqh, wql, wqb, nullptr, Qhp, Qlp, fcos, fsin, CC);
    gemm_bf<2><<<dim3(1, MTOT / 128), 256, G2SMEM>>>(
        xh, xl, wkh, wkl, wkb, nullptr, Khp, Klp, fcos, fsin, DD);
    gemm_bf<3><<<dim3(1, MTOT / 128), 256, G2SMEM>>>(
        xh, xl, wvh, wvl, wvb, nullptr, Vhp, Vlp, nullptr, nullptr, DD);

    // 3. flash attention (heavy-first schedule)
    attn_mma<<<512, 256, A_SMEM>>>(Qhp, Qlp, Khp, Klp, Vhp, Vlp, Ohp, Olp);

    // 4. output projection -> d_out
    gemm_bf<0><<<dim3(CC / 128, MTOT / 128), 256, G2SMEM>>>(
        Ohp, Olp, woh, wol, wob, out, nullptr, nullptr, nullptr, nullptr, CC);
}

// round 6
// speedup vs baseline: 4.2110x; 1.1717x over previous
#include <cuda_runtime.h>
#include <cuda_bf16.h>
#include <cstdint>

#define BB 2
#define TT 2048
#define CC 2048
#define HH 16
#define DD 128
#define MTOT (BB * TT)   // 4096
#define KTOT CC          // all GEMMs have K = 2048
#define NQKV 2304        // fused QKV output width: 2048 + 128 + 128
#define SMSCALE 0.08838834764831845f   // 1/sqrt(128)

typedef __nv_bfloat16 bf16;

// ---------------------------------------------------------------------------
// Scratch (allocation-free: __device__ globals)
// ---------------------------------------------------------------------------
__device__ bf16 g_xh[(size_t)MTOT * CC],  g_xl[(size_t)MTOT * CC];
__device__ bf16 g_wh[(size_t)KTOT * NQKV], g_wl[(size_t)KTOT * NQKV];  // packed QKV W
__device__ bf16 g_woh[(size_t)CC * CC],   g_wol[(size_t)CC * CC];
__device__ float g_bias[NQKV];

__device__ bf16 g_Qh[(size_t)MTOT * CC],  g_Ql[(size_t)MTOT * CC];  // [B,H,T,D]
__device__ bf16 g_Kh[(size_t)MTOT * DD],  g_Kl[(size_t)MTOT * DD];  // [B,T,D]
__device__ bf16 g_Vh[(size_t)MTOT * DD],  g_Vl[(size_t)MTOT * DD];  // [B,T,D]
__device__ bf16 g_Oh[(size_t)MTOT * CC],  g_Ol[(size_t)MTOT * CC];  // [B,T,H*D]

// ---------------------------------------------------------------------------
// PTX helpers
// ---------------------------------------------------------------------------
__device__ __forceinline__ uint32_t smem_u32(const void* p) {
    uint32_t a;
    asm("{ .reg .u64 t; cvta.to.shared.u64 t, %1; cvt.u32.u64 %0, t; }"
        : "=r"(a) : "l"(p));
    return a;
}

#define LDSM_X4(r0, r1, r2, r3, addr) \
    asm volatile("ldmatrix.sync.aligned.m8n8.x4.shared.b16 {%0,%1,%2,%3}, [%4];" \
                 : "=r"(r0), "=r"(r1), "=r"(r2), "=r"(r3) : "r"(addr))
#define LDSM_X4_T(r0, r1, r2, r3, addr) \
    asm volatile("ldmatrix.sync.aligned.m8n8.x4.trans.shared.b16 {%0,%1,%2,%3}, [%4];" \
                 : "=r"(r0), "=r"(r1), "=r"(r2), "=r"(r3) : "r"(addr))

#define MMA_BF16(d, a, b0v, b1v) \
    asm volatile("mma.sync.aligned.m16n8k16.row.col.f32.bf16.bf16.f32 " \
                 "{%0,%1,%2,%3}, {%4,%5,%6,%7}, {%8,%9}, {%0,%1,%2,%3};" \
                 : "+f"((d)[0]), "+f"((d)[1]), "+f"((d)[2]), "+f"((d)[3]) \
                 : "r"((a)[0]), "r"((a)[1]), "r"((a)[2]), "r"((a)[3]), \
                   "r"(b0v), "r"(b1v))

#define CP16(dst, src) \
    asm volatile("cp.async.cg.shared.global [%0], [%1], 16;" :: "r"(dst), "l"(src))
#define CP_COMMIT() asm volatile("cp.async.commit_group;" ::: "memory")
#define CP_WAIT(n)  asm volatile("cp.async.wait_group %0;" :: "n"(n) : "memory")

__device__ __forceinline__ uint32_t pack_bf2(bf16 a, bf16 b) {
    return ((uint32_t)__bfloat16_as_ushort(b) << 16) | (uint32_t)__bfloat16_as_ushort(a);
}
__device__ __forceinline__ void split2(float x, float y, uint32_t& hi, uint32_t& lo) {
    bf16 hx = __float2bfloat16(x), hy = __float2bfloat16(y);
    hi = pack_bf2(hx, hy);
    lo = pack_bf2(__float2bfloat16(x - __bfloat162float(hx)),
                  __float2bfloat16(y - __bfloat162float(hy)));
}

// ---------------------------------------------------------------------------
// Elementwise fp32 -> (bf16 hi, bf16 lo), contiguous. n4 = n/4.
// ---------------------------------------------------------------------------
__global__ __launch_bounds__(256) void split_kernel(
    const float* __restrict__ in, bf16* __restrict__ hi, bf16* __restrict__ lo, int n4)
{
    int i = blockIdx.x * 256 + threadIdx.x;
    if (i >= n4) return;
    float4 v = ((const float4*)in)[i];
    uint32_t h0, l0, h1, l1;
    split2(v.x, v.y, h0, l0);
    split2(v.z, v.w, h1, l1);
    ((uint2*)hi)[i] = make_uint2(h0, h1);
    ((uint2*)lo)[i] = make_uint2(l0, l1);
}

// Strided variant: input [K][2^shift] row-major -> output rows with stride NQKV.
// hi/lo pointers are pre-offset to the destination column block.
__global__ __launch_bounds__(256) void split_stride_kernel(
    const float* __restrict__ in, bf16* __restrict__ hi, bf16* __restrict__ lo,
    int shift, int n4)
{
    int i = blockIdx.x * 256 + threadIdx.x;
    if (i >= n4) return;
    int row = i >> (shift - 2);
    int col = (i << 2) & ((1 << shift) - 1);
    float4 v = ((const float4*)in)[i];
    uint32_t h0, l0, h1, l1;
    split2(v.x, v.y, h0, l0);
    split2(v.z, v.w, h1, l1);
    size_t o = (size_t)row * NQKV + col;
    *(uint2*)(hi + o) = make_uint2(h0, h1);
    *(uint2*)(lo + o) = make_uint2(l0, l1);
}

__global__ void pack_bias_kernel(const float* __restrict__ qb,
                                 const float* __restrict__ kb,
                                 const float* __restrict__ vb,
                                 float* __restrict__ out)
{
    int i = blockIdx.x * 256 + threadIdx.x;
    if (i < 2048)      out[i] = qb[i];
    else if (i < 2176) out[i] = kb[i - 2048];
    else if (i < 2304) out[i] = vb[i - 2176];
}

// ---------------------------------------------------------------------------
// Shared GEMM tile machinery: BM=128 BN=128 BK=32, 256 thr, cp.async 3-stage.
// ---------------------------------------------------------------------------
#define STG_BYTES 32768
#define G2SMEM (3 * STG_BYTES)
#define NITER (KTOT / 32)   // 64

__device__ __forceinline__ uint32_t a_off(int r, int c) {
    return (uint32_t)(r * 64 + ((c ^ ((r >> 1) & 3)) << 4));
}
__device__ __forceinline__ uint32_t b_off(int r, int c) {
    return (uint32_t)(r * 256 + ((c ^ (r & 7)) << 4));
}

__device__ __forceinline__ void g2s_issue(
    uint32_t stg, const bf16* __restrict__ Ah, const bf16* __restrict__ Al,
    const bf16* __restrict__ Wh, const bf16* __restrict__ Wl,
    int N, int m0, int n0, int k0, int tid)
{
#pragma unroll
    for (int p = 0; p < 2; p++) {
        int cid = p * 256 + tid;
        int r = cid >> 2, c = cid & 3;
        size_t gs = (size_t)(m0 + r) * KTOT + k0 + c * 8;
        uint32_t off = a_off(r, c);
        CP16(stg + off, Ah + gs);
        CP16(stg + 8192 + off, Al + gs);
    }
#pragma unroll
    for (int p = 0; p < 2; p++) {
        int cid = p * 256 + tid;
        int r = cid >> 4, c = cid & 15;
        size_t gs = (size_t)(k0 + r) * N + n0 + c * 8;
        uint32_t off = b_off(r, c);
        CP16(stg + 16384 + off, Wh + gs);
        CP16(stg + 24576 + off, Wl + gs);
    }
}

// Mainloop: accumulates 128x128 tile into acc. Returns after NITER iterations.
__device__ __forceinline__ void gemm_mainloop(
    uint32_t sb, const bf16* Ah, const bf16* Al, const bf16* Wh, const bf16* Wl,
    int N, int m0, int n0, int tid, int lane, int wm, int wn, float acc[2][8][4])
{
    const int lrow = lane & 15;
    const int lsel = lane >> 4;

    g2s_issue(sb, Ah, Al, Wh, Wl, N, m0, n0, 0, tid);
    CP_COMMIT();
    g2s_issue(sb + STG_BYTES, Ah, Al, Wh, Wl, N, m0, n0, 32, tid);
    CP_COMMIT();

    for (int it = 0; it < NITER; it++) {
        if (it == NITER - 1) CP_WAIT(0); else CP_WAIT(1);
        __syncthreads();
        if (it + 2 < NITER) {
            g2s_issue(sb + ((it + 2) % 3) * STG_BYTES, Ah, Al, Wh, Wl, N,
                      m0, n0, (it + 2) * 32, tid);
            CP_COMMIT();
        }

        const uint32_t stA = sb + (uint32_t)(it % 3) * STG_BYTES;
        const uint32_t stB = stA + 16384;

#pragma unroll
        for (int ks = 0; ks < 2; ks++) {
            uint32_t ah[2][4], al[2][4];
#pragma unroll
            for (int mf = 0; mf < 2; mf++) {
                int row = wm * 32 + mf * 16 + lrow;
                int chunk = ks * 2 + lsel;
                uint32_t addr = stA + a_off(row, chunk);
                LDSM_X4(ah[mf][0], ah[mf][1], ah[mf][2], ah[mf][3], addr);
                LDSM_X4(al[mf][0], al[mf][1], al[mf][2], al[mf][3], addr + 8192);
            }
#pragma unroll
            for (int nj = 0; nj < 4; nj++) {
                int brow = ks * 16 + lrow;
                int bchunk = wn * 8 + nj * 2 + lsel;
                uint32_t baddr = stB + b_off(brow, bchunk);
                uint32_t bh[4], bl[4];
                LDSM_X4_T(bh[0], bh[1], bh[2], bh[3], baddr);
                LDSM_X4_T(bl[0], bl[1], bl[2], bl[3], baddr + 8192);
#pragma unroll
                for (int mf = 0; mf < 2; mf++) {
                    MMA_BF16(acc[mf][2 * nj],     ah[mf], bh[0], bh[1]);
                    MMA_BF16(acc[mf][2 * nj],     ah[mf], bl[0], bl[1]);
                    MMA_BF16(acc[mf][2 * nj],     al[mf], bh[0], bh[1]);
                    MMA_BF16(acc[mf][2 * nj + 1], ah[mf], bh[2], bh[3]);
                    MMA_BF16(acc[mf][2 * nj + 1], ah[mf], bl[2], bl[3]);
                    MMA_BF16(acc[mf][2 * nj + 1], al[mf], bh[2], bh[3]);
                }
            }
        }
    }
}

// ---------------------------------------------------------------------------
// Fused QKV GEMM: Out = x @ [wq|wk|wv] + bias over N=2304.
// CTA-x 0..15 -> Q (RoPE+scale, [B,H,T,D]); 16 -> K (RoPE, [B,T,D]); 17 -> V.
// ---------------------------------------------------------------------------
__global__ __launch_bounds__(256, 2)
void gemm_qkv(const bf16* __restrict__ Ah, const bf16* __restrict__ Al,
              const bf16* __restrict__ Wh, const bf16* __restrict__ Wl,
              const float* __restrict__ bias,
              bf16* __restrict__ Qh, bf16* __restrict__ Ql,
              bf16* __restrict__ Kh, bf16* __restrict__ Kl,
              bf16* __restrict__ Vh, bf16* __restrict__ Vl,
              const float* __restrict__ cs, const float* __restrict__ sn)
{
    extern __shared__ char sm[];
    const uint32_t sb = smem_u32(sm);
    const int tid  = threadIdx.x;
    const int lane = tid & 31;
    const int wid  = tid >> 5;
    const int wm   = wid >> 1;
    const int wn   = wid & 1;
    const int bxid = blockIdx.x;
    const int m0   = blockIdx.y * 128;
    const int n0   = bxid * 128;

    float acc[2][8][4];
#pragma unroll
    for (int i = 0; i < 2; i++)
#pragma unroll
        for (int j = 0; j < 8; j++)
#pragma unroll
            for (int q = 0; q < 4; q++) acc[i][j][q] = 0.f;

    gemm_mainloop(sb, Ah, Al, Wh, Wl, NQKV, m0, n0, tid, lane, wm, wn, acc);

    const int g = lane >> 2, t = lane & 3;
#pragma unroll
    for (int mf = 0; mf < 2; mf++) {
        int row0 = m0 + wm * 32 + mf * 16 + g;
#pragma unroll
        for (int nt = 0; nt < 8; nt++) {
            int col = n0 + wn * 64 + nt * 8 + 2 * t;
            float2 bi = *(const float2*)(bias + col);
            float a0 = acc[mf][nt][0] + bi.x, a1 = acc[mf][nt][1] + bi.y;
            float a2 = acc[mf][nt][2] + bi.x, a3 = acc[mf][nt][3] + bi.y;
            if (bxid < 16) {
                // Q: RoPE + scale + split -> [B,H,T,D]
                int f = (col & 127) >> 1;
#pragma unroll
                for (int rr = 0; rr < 2; rr++) {
                    int r = row0 + rr * 8;
                    int tloc = r & (TT - 1);
                    float c = cs[tloc * 64 + f], s = sn[tloc * 64 + f];
                    float re = rr ? a2 : a0, im = rr ? a3 : a1;
                    float ore = (re * c - im * s) * SMSCALE;
                    float oim = (re * s + im * c) * SMSCALE;
                    uint32_t hi, lo;
                    split2(ore, oim, hi, lo);
                    int bq = r >> 11, hq = col >> 7;
                    size_t idx = ((size_t)(bq * HH + hq) * TT + tloc) * DD + (col & 127);
                    *(uint32_t*)(Qh + idx) = hi;
                    *(uint32_t*)(Ql + idx) = lo;
                }
            } else if (bxid == 16) {
                // K: RoPE + split -> [B,T,D]
                int colp = col - 2048;
                int f = colp >> 1;
#pragma unroll
                for (int rr = 0; rr < 2; rr++) {
                    int r = row0 + rr * 8;
                    int tloc = r & (TT - 1);
                    float c = cs[tloc * 64 + f], s = sn[tloc * 64 + f];
                    float re = rr ? a2 : a0, im = rr ? a3 : a1;
                    float ore = re * c - im * s;
                    float oim = re * s + im * c;
                    uint32_t hi, lo;
                    split2(ore, oim, hi, lo);
                    size_t idx = (size_t)r * DD + colp;
                    *(uint32_t*)(Kh + idx) = hi;
                    *(uint32_t*)(Kl + idx) = lo;
                }
            } else {
                // V: split -> [B,T,D]
                int colp = col - 2176;
                uint32_t hi, lo;
                split2(a0, a1, hi, lo);
                *(uint32_t*)(Vh + (size_t)row0 * DD + colp) = hi;
                *(uint32_t*)(Vl + (size_t)row0 * DD + colp) = lo;
                split2(a2, a3, hi, lo);
                *(uint32_t*)(Vh + (size_t)(row0 + 8) * DD + colp) = hi;
                *(uint32_t*)(Vl + (size_t)(row0 + 8) * DD + colp) = lo;
            }
        }
    }
}

// ---------------------------------------------------------------------------
// Output GEMM: out = O @ wo + bias (fp32 out, N=2048)
// ---------------------------------------------------------------------------
__global__ __launch_bounds__(256, 2)
void gemm_out(const bf16* __restrict__ Ah, const bf16* __restrict__ Al,
              const bf16* __restrict__ Wh, const bf16* __restrict__ Wl,
              const float* __restrict__ bias, float* __restrict__ OutF)
{
    extern __shared__ char sm[];
    const uint32_t sb = smem_u32(sm);
    const int tid  = threadIdx.x;
    const int lane = tid & 31;
    const int wid  = tid >> 5;
    const int wm   = wid >> 1;
    const int wn   = wid & 1;
    const int m0   = blockIdx.y * 128;
    const int n0   = blockIdx.x * 128;

    float acc[2][8][4];
#pragma unroll
    for (int i = 0; i < 2; i++)
#pragma unroll
        for (int j = 0; j < 8; j++)
#pragma unroll
            for (int q = 0; q < 4; q++) acc[i][j][q] = 0.f;

    gemm_mainloop(sb, Ah, Al, Wh, Wl, CC, m0, n0, tid, lane, wm, wn, acc);

    const int g = lane >> 2, t = lane & 3;
#pragma unroll
    for (int mf = 0; mf < 2; mf++) {
        int row0 = m0 + wm * 32 + mf * 16 + g;
#pragma unroll
        for (int nt = 0; nt < 8; nt++) {
            int col = n0 + wn * 64 + nt * 8 + 2 * t;
            float2 bi = *(const float2*)(bias + col);
            *(float2*)(OutF + (size_t)row0 * CC + col) =
                make_float2(acc[mf][nt][0] + bi.x, acc[mf][nt][1] + bi.y);
            *(float2*)(OutF + (size_t)(row0 + 8) * CC + col) =
                make_float2(acc[mf][nt][2] + bi.x, acc[mf][nt][3] + bi.y);
        }
    }
}

// ---------------------------------------------------------------------------
// Flash attention on mma.sync: BM=128 (8 warps x 16 rows), BN=64, D=128.
// 1D grid, heaviest Q-tiles scheduled first.
// ---------------------------------------------------------------------------
#define AQ_H 0u
#define AQ_L 32768u
#define AKV(s) (65536u + (uint32_t)(s) * 65536u)
#define A_SMEM 196608

__device__ __forceinline__ uint32_t toff(int r, int c) {
    return (uint32_t)(r * 256 + ((c ^ (r & 7)) << 4));
}

__global__ __launch_bounds__(256, 1) void attn_mma(
    const bf16* __restrict__ Qh, const bf16* __restrict__ Ql,
    const bf16* __restrict__ Kh, const bf16* __restrict__ Kl,
    const bf16* __restrict__ Vh, const bf16* __restrict__ Vl,
    bf16* __restrict__ Oh, bf16* __restrict__ Ol)
{
    extern __shared__ char sm[];
    const uint32_t sb = smem_u32(sm);
    const int tid = threadIdx.x, lane = tid & 31, w = tid >> 5;
    const int id = blockIdx.x;
    const int bx = (TT / 128 - 1) - (id >> 5);
    const int hb = id & 31;
    const int h  = hb & 15;
    const int b  = hb >> 4;
    const int i0 = bx * 128;
    const int jtmax = 2 * bx + 1;

    const size_t qbase  = ((size_t)(b * HH + h) * TT + i0) * DD;
    const size_t kvbase = (size_t)b * TT * DD;

#pragma unroll
    for (int i = 0; i < 8; i++) {
        int cid = i * 256 + tid;
        int r = cid >> 4, c = cid & 15;
        size_t gs = qbase + (size_t)r * DD + c * 8;
        uint32_t off = toff(r, c);
        CP16(sb + AQ_H + off, Qh + gs);
        CP16(sb + AQ_L + off, Ql + gs);
    }
#pragma unroll
    for (int i = 0; i < 4; i++) {
        int cid = i * 256 + tid;
        int r = cid >> 4, c = cid & 15;
        size_t gs = kvbase + (size_t)r * DD + c * 8;
        uint32_t off = toff(r, c);
        CP16(sb + AKV(0) + off,          Kh + gs);
        CP16(sb + AKV(0) + 16384 + off,  Kl + gs);
        CP16(sb + AKV(0) + 32768 + off,  Vh + gs);
        CP16(sb + AKV(0) + 49152 + off,  Vl + gs);
    }
    CP_COMMIT();

    const int lrA = lane & 15;
    const int lsA = lane >> 4;
    const int lrB = (lane & 7) + ((lane >> 4) << 3);
    const int csB = (lane >> 3) & 1;
    const int g = lane >> 2, t = lane & 3;

    float oa[16][4];
#pragma unroll
    for (int i = 0; i < 16; i++)
#pragma unroll
        for (int j = 0; j < 4; j++) oa[i][j] = 0.f;
    float m0r = -1e30f, m1r = -1e30f, l0r = 0.f, l1r = 0.f;

    for (int jt = 0; jt <= jtmax; jt++) {
        if (jt > 0) __syncthreads();
        if (jt + 1 <= jtmax) {
            uint32_t stg = AKV((jt + 1) & 1);
#pragma unroll
            for (int i = 0; i < 4; i++) {
                int cid = i * 256 + tid;
                int r = cid >> 4, c = cid & 15;
                size_t gs = kvbase + (size_t)((jt + 1) * 64 + r) * DD + c * 8;
                uint32_t off = toff(r, c);
                CP16(sb + stg + off,          Kh + gs);
                CP16(sb + stg + 16384 + off,  Kl + gs);
                CP16(sb + stg + 32768 + off,  Vh + gs);
                CP16(sb + stg + 49152 + off,  Vl + gs);
            }
            CP_COMMIT();
            CP_WAIT(1);
        } else {
            CP_WAIT(0);
        }
        __syncthreads();

        if (64 * jt > i0 + 16 * w + 15) continue;

        const uint32_t kvs = sb + AKV(jt & 1);

        // ---- S = Q K^T ----
        float sa[8][4];
#pragma unroll
        for (int i = 0; i < 8; i++)
#pragma unroll
            for (int j = 0; j < 4; j++) sa[i][j] = 0.f;

#pragma unroll
        for (int ks = 0; ks < 8; ks++) {
            uint32_t ah[4], al[4];
            uint32_t qaddr = sb + AQ_H + toff(16 * w + lrA, 2 * ks + lsA);
            LDSM_X4(ah[0], ah[1], ah[2], ah[3], qaddr);
            LDSM_X4(al[0], al[1], al[2], al[3], qaddr + AQ_L - AQ_H);
#pragma unroll
            for (int np = 0; np < 4; np++) {
                uint32_t kaddr = kvs + toff(np * 16 + lrB, 2 * ks + csB);
                uint32_t bh[4], bl[4];
                LDSM_X4(bh[0], bh[1], bh[2], bh[3], kaddr);
                LDSM_X4(bl[0], bl[1], bl[2], bl[3], kaddr + 16384);
                MMA_BF16(sa[2 * np],     ah, bh[0], bh[1]);
                MMA_BF16(sa[2 * np],     ah, bl[0], bl[1]);
                MMA_BF16(sa[2 * np],     al, bh[0], bh[1]);
                MMA_BF16(sa[2 * np + 1], ah, bh[2], bh[3]);
                MMA_BF16(sa[2 * np + 1], ah, bl[2], bl[3]);
                MMA_BF16(sa[2 * np + 1], al, bh[2], bh[3]);
            }
        }

        // ---- causal mask ----
        if (64 * jt + 63 > i0 + 16 * w) {
            int r0g = i0 + 16 * w + g;
#pragma unroll
            for (int nf = 0; nf < 8; nf++) {
                int cg = 64 * jt + nf * 8 + 2 * t;
                if (cg     > r0g)     sa[nf][0] = -1e30f;
                if (cg + 1 > r0g)     sa[nf][1] = -1e30f;
                if (cg     > r0g + 8) sa[nf][2] = -1e30f;
                if (cg + 1 > r0g + 8) sa[nf][3] = -1e30f;
            }
        }

        // ---- online softmax ----
        float mx0 = -1e30f, mx1 = -1e30f;
#pragma unroll
        for (int nf = 0; nf < 8; nf++) {
            mx0 = fmaxf(mx0, fmaxf(sa[nf][0], sa[nf][1]));
            mx1 = fmaxf(mx1, fmaxf(sa[nf][2], sa[nf][3]));
        }
        mx0 = fmaxf(mx0, __shfl_xor_sync(0xffffffffu, mx0, 1));
        mx0 = fmaxf(mx0, __shfl_xor_sync(0xffffffffu, mx0, 2));
        mx1 = fmaxf(mx1, __shfl_xor_sync(0xffffffffu, mx1, 1));
        mx1 = fmaxf(mx1, __shfl_xor_sync(0xffffffffu, mx1, 2));
        float mn0 = fmaxf(m0r, mx0), mn1 = fmaxf(m1r, mx1);

        float sum0 = 0.f, sum1 = 0.f;
#pragma unroll
        for (int nf = 0; nf < 8; nf++) {
            sa[nf][0] = __expf(sa[nf][0] - mn0);
            sa[nf][1] = __expf(sa[nf][1] - mn0);
            sa[nf][2] = __expf(sa[nf][2] - mn1);
            sa[nf][3] = __expf(sa[nf][3] - mn1);
            sum0 += sa[nf][0] + sa[nf][1];
            sum1 += sa[nf][2] + sa[nf][3];
        }
        sum0 += __shfl_xor_sync(0xffffffffu, sum0, 1);
        sum0 += __shfl_xor_sync(0xffffffffu, sum0, 2);
        sum1 += __shfl_xor_sync(0xffffffffu, sum1, 1);
        sum1 += __shfl_xor_sync(0xffffffffu, sum1, 2);

        float scl0 = __expf(m0r - mn0), scl1 = __expf(m1r - mn1);
        l0r = l0r * scl0 + sum0;
        l1r = l1r * scl1 + sum1;
        m0r = mn0; m1r = mn1;

#pragma unroll
        for (int nf = 0; nf < 16; nf++) {
            oa[nf][0] *= scl0; oa[nf][1] *= scl0;
            oa[nf][2] *= scl1; oa[nf][3] *= scl1;
        }

        // ---- O += P V ----
#pragma unroll
        for (int s = 0; s < 4; s++) {
            uint32_t aPh[4], aPl[4];
            split2(sa[2 * s][0],     sa[2 * s][1],     aPh[0], aPl[0]);
            split2(sa[2 * s][2],     sa[2 * s][3],     aPh[1], aPl[1]);
            split2(sa[2 * s + 1][0], sa[2 * s + 1][1], aPh[2], aPl[2]);
            split2(sa[2 * s + 1][2], sa[2 * s + 1][3], aPh[3], aPl[3]);
#pragma unroll
            for (int np = 0; np < 8; np++) {
                uint32_t vaddr = kvs + 32768 + toff(s * 16 + lrA, 2 * np + lsA);
                uint32_t bh[4], bl[4];
                LDSM_X4_T(bh[0], bh[1], bh[2], bh[3], vaddr);
                LDSM_X4_T(bl[0], bl[1], bl[2], bl[3], vaddr + 16384);
                MMA_BF16(oa[2 * np],     aPh, bh[0], bh[1]);
                MMA_BF16(oa[2 * np],     aPh, bl[0], bl[1]);
                MMA_BF16(oa[2 * np],     aPl, bh[0], bh[1]);
                MMA_BF16(oa[2 * np + 1], aPh, bh[2], bh[3]);
                MMA_BF16(oa[2 * np + 1], aPh, bl[2], bl[3]);
                MMA_BF16(oa[2 * np + 1], aPl, bh[2], bh[3]);
            }
        }
    }

    // ---- epilogue ----
    float inv0 = 1.f / l0r, inv1 = 1.f / l1r;
    size_t or0 = (size_t)(b * TT + i0 + 16 * w + g) * CC + h * DD;
    size_t or1 = or0 + (size_t)8 * CC;
#pragma unroll
    for (int nf = 0; nf < 16; nf++) {
        int col = nf * 8 + 2 * t;
        uint32_t hi, lo;
        split2(oa[nf][0] * inv0, oa[nf][1] * inv0, hi, lo);
        *(uint32_t*)(Oh + or0 + col) = hi;
        *(uint32_t*)(Ol + or0 + col) = lo;
        split2(oa[nf][2] * inv1, oa[nf][3] * inv1, hi, lo);
        *(uint32_t*)(Oh + or1 + col) = hi;
        *(uint32_t*)(Ol + or1 + col) = lo;
    }
}

// ---------------------------------------------------------------------------
// Launcher
// ---------------------------------------------------------------------------
extern "C" void kernel_launch(void* const* d_in, const int* in_sizes, int n_in,
                              void* d_out, int out_size)
{
    const float* x    = (const float*)d_in[0];
    const float* fcos = (const float*)d_in[1];
    const float* fsin = (const float*)d_in[2];
    const float* wq   = (const float*)d_in[4];
    const float* wqb  = (const float*)d_in[5];
    const float* wk   = (const float*)d_in[6];
    const float* wkb  = (const float*)d_in[7];
    const float* wv   = (const float*)d_in[8];
    const float* wvb  = (const float*)d_in[9];
    const float* wo   = (const float*)d_in[10];
    const float* wob  = (const float*)d_in[11];
    float* out = (float*)d_out;

    bf16 *xh, *xl, *wh, *wl, *woh, *wol;
    bf16 *Qhp, *Qlp, *Khp, *Klp, *Vhp, *Vlp, *Ohp, *Olp;
    float* biasp;
    cudaGetSymbolAddress((void**)&xh, g_xh);   cudaGetSymbolAddress((void**)&xl, g_xl);
    cudaGetSymbolAddress((void**)&wh, g_wh);   cudaGetSymbolAddress((void**)&wl, g_wl);
    cudaGetSymbolAddress((void**)&woh, g_woh); cudaGetSymbolAddress((void**)&wol, g_wol);
    cudaGetSymbolAddress((void**)&biasp, g_bias);
    cudaGetSymbolAddress((void**)&Qhp, g_Qh);  cudaGetSymbolAddress((void**)&Qlp, g_Ql);
    cudaGetSymbolAddress((void**)&Khp, g_Kh);  cudaGetSymbolAddress((void**)&Klp, g_Kl);
    cudaGetSymbolAddress((void**)&Vhp, g_Vh);  cudaGetSymbolAddress((void**)&Vlp, g_Vl);
    cudaGetSymbolAddress((void**)&Ohp, g_Oh);  cudaGetSymbolAddress((void**)&Olp, g_Ol);

    cudaFuncSetAttribute(gemm_qkv, cudaFuncAttributeMaxDynamicSharedMemorySize, G2SMEM);
    cudaFuncSetAttribute(gemm_out, cudaFuncAttributeMaxDynamicSharedMemorySize, G2SMEM);
    cudaFuncSetAttribute(attn_mma, cudaFuncAttributeMaxDynamicSharedMemorySize, A_SMEM);

    // 1. splits: x, packed QKV weights, wo, bias
    split_kernel<<<8192, 256>>>(x,  xh,  xl,  MTOT * CC / 4);
    split_stride_kernel<<<4096, 256>>>(wq, wh,        wl,        11, CC * CC / 4);
    split_stride_kernel<<<256,  256>>>(wk, wh + 2048, wl + 2048,  7, CC * DD / 4);
    split_stride_kernel<<<256,  256>>>(wv, wh + 2176, wl + 2176,  7, CC * DD / 4);
    split_kernel<<<4096, 256>>>(wo, woh, wol, CC * CC / 4);
    pack_bias_kernel<<<9, 256>>>(wqb, wkb, wvb, biasp);

    // 2. fused QKV projection (RoPE/scale/split epilogues per CTA column block)
    gemm_qkv<<<dim3(NQKV / 128, MTOT / 128), 256, G2SMEM>>>(
        xh, xl, wh, wl, biasp, Qhp, Qlp, Khp, Klp, Vhp, Vlp, fcos, fsin);

    // 3. flash attention (heavy-first schedule)
    attn_mma<<<512, 256, A_SMEM>>>(Qhp, Qlp, Khp, Klp, Vhp, Vlp, Ohp, Olp);

    // 4. output projection -> d_out
    gemm_out<<<dim3(CC / 128, MTOT / 128), 256, G2SMEM>>>(
        Ohp, Olp, woh, wol, wob, out);
}

// round 7
// speedup vs baseline: 4.2953x; 1.0200x over previous
#include <cuda_runtime.h>
#include <cuda_bf16.h>
#include <cstdint>

#define BB 2
#define TT 2048
#define CC 2048
#define HH 16
#define DD 128
#define MTOT (BB * TT)   // 4096
#define KTOT CC          // all GEMMs have K = 2048
#define NQKV 2304        // fused QKV output width: 2048 + 128 + 128
// 1/sqrt(128) * log2(e): softmax done in base-2
#define QSCALE (0.08838834764831845f * 1.44269504088896340f)

typedef __nv_bfloat16 bf16;

// ---------------------------------------------------------------------------
// Scratch (allocation-free: __device__ globals)
// ---------------------------------------------------------------------------
__device__ bf16 g_xh[(size_t)MTOT * CC],  g_xl[(size_t)MTOT * CC];
__device__ bf16 g_wh[(size_t)KTOT * NQKV], g_wl[(size_t)KTOT * NQKV];  // packed QKV W
__device__ bf16 g_woh[(size_t)CC * CC],   g_wol[(size_t)CC * CC];
__device__ float g_bias[NQKV];

__device__ bf16 g_Qh[(size_t)MTOT * CC],  g_Ql[(size_t)MTOT * CC];  // [B,H,T,D]
__device__ bf16 g_Kh[(size_t)MTOT * DD],  g_Kl[(size_t)MTOT * DD];  // [B,T,D]
__device__ bf16 g_Vh[(size_t)MTOT * DD],  g_Vl[(size_t)MTOT * DD];  // [B,T,D]
__device__ bf16 g_Oh[(size_t)MTOT * CC],  g_Ol[(size_t)MTOT * CC];  // [B,T,H*D]

// ---------------------------------------------------------------------------
// PTX helpers
// ---------------------------------------------------------------------------
__device__ __forceinline__ uint32_t smem_u32(const void* p) {
    uint32_t a;
    asm("{ .reg .u64 t; cvta.to.shared.u64 t, %1; cvt.u32.u64 %0, t; }"
        : "=r"(a) : "l"(p));
    return a;
}
__device__ __forceinline__ float ex2(float x) {
    float y;
    asm("ex2.approx.ftz.f32 %0, %1;" : "=f"(y) : "f"(x));
    return y;
}

#define LDSM_X4(r0, r1, r2, r3, addr) \
    asm volatile("ldmatrix.sync.aligned.m8n8.x4.shared.b16 {%0,%1,%2,%3}, [%4];" \
                 : "=r"(r0), "=r"(r1), "=r"(r2), "=r"(r3) : "r"(addr))
#define LDSM_X4_T(r0, r1, r2, r3, addr) \
    asm volatile("ldmatrix.sync.aligned.m8n8.x4.trans.shared.b16 {%0,%1,%2,%3}, [%4];" \
                 : "=r"(r0), "=r"(r1), "=r"(r2), "=r"(r3) : "r"(addr))

#define MMA_BF16(d, a, b0v, b1v) \
    asm volatile("mma.sync.aligned.m16n8k16.row.col.f32.bf16.bf16.f32 " \
                 "{%0,%1,%2,%3}, {%4,%5,%6,%7}, {%8,%9}, {%0,%1,%2,%3};" \
                 : "+f"((d)[0]), "+f"((d)[1]), "+f"((d)[2]), "+f"((d)[3]) \
                 : "r"((a)[0]), "r"((a)[1]), "r"((a)[2]), "r"((a)[3]), \
                   "r"(b0v), "r"(b1v))

#define CP16(dst, src) \
    asm volatile("cp.async.cg.shared.global [%0], [%1], 16;" :: "r"(dst), "l"(src))
#define CP_COMMIT() asm volatile("cp.async.commit_group;" ::: "memory")
#define CP_WAIT(n)  asm volatile("cp.async.wait_group %0;" :: "n"(n) : "memory")

__device__ __forceinline__ uint32_t pack_bf2(bf16 a, bf16 b) {
    return ((uint32_t)__bfloat16_as_ushort(b) << 16) | (uint32_t)__bfloat16_as_ushort(a);
}
__device__ __forceinline__ void split2(float x, float y, uint32_t& hi, uint32_t& lo) {
    bf16 hx = __float2bfloat16(x), hy = __float2bfloat16(y);
    hi = pack_bf2(hx, hy);
    lo = pack_bf2(__float2bfloat16(x - __bfloat162float(hx)),
                  __float2bfloat16(y - __bfloat162float(hy)));
}

// ---------------------------------------------------------------------------
// One merged prep kernel: all fp32->bf16 hi/lo splits + bias pack.
// Block ranges: [0,8192) x | [8192,12288) wq | [12288,12544) wk |
// [12544,12800) wv | [12800,16896) wo | [16896,16905) bias
// ---------------------------------------------------------------------------
__global__ __launch_bounds__(256) void prep_kernel(
    const float* __restrict__ x,  const float* __restrict__ wq,
    const float* __restrict__ wk, const float* __restrict__ wv,
    const float* __restrict__ wo,
    const float* __restrict__ qb, const float* __restrict__ kb,
    const float* __restrict__ vb,
    bf16* __restrict__ xh, bf16* __restrict__ xl,
    bf16* __restrict__ wh, bf16* __restrict__ wl,
    bf16* __restrict__ woh, bf16* __restrict__ wol,
    float* __restrict__ bias)
{
    int blk = blockIdx.x;
    int tid = threadIdx.x;
    if (blk < 8192) {                     // x: contiguous
        int i = blk * 256 + tid;
        float4 v = ((const float4*)x)[i];
        uint32_t h0, l0, h1, l1;
        split2(v.x, v.y, h0, l0);
        split2(v.z, v.w, h1, l1);
        ((uint2*)xh)[i] = make_uint2(h0, h1);
        ((uint2*)xl)[i] = make_uint2(l0, l1);
    } else if (blk < 12288) {             // wq: [2048][2048] -> cols 0..2047 of wh
        int i = (blk - 8192) * 256 + tid;
        int row = i >> 9, col = (i << 2) & 2047;
        float4 v = ((const float4*)wq)[i];
        uint32_t h0, l0, h1, l1;
        split2(v.x, v.y, h0, l0);
        split2(v.z, v.w, h1, l1);
        size_t o = (size_t)row * NQKV + col;
        *(uint2*)(wh + o) = make_uint2(h0, h1);
        *(uint2*)(wl + o) = make_uint2(l0, l1);
    } else if (blk < 12544) {             // wk: [2048][128] -> cols 2048..2175
        int i = (blk - 12288) * 256 + tid;
        int row = i >> 5, col = (i << 2) & 127;
        float4 v = ((const float4*)wk)[i];
        uint32_t h0, l0, h1, l1;
        split2(v.x, v.y, h0, l0);
        split2(v.z, v.w, h1, l1);
        size_t o = (size_t)row * NQKV + 2048 + col;
        *(uint2*)(wh + o) = make_uint2(h0, h1);
        *(uint2*)(wl + o) = make_uint2(l0, l1);
    } else if (blk < 12800) {             // wv: [2048][128] -> cols 2176..2303
        int i = (blk - 12544) * 256 + tid;
        int row = i >> 5, col = (i << 2) & 127;
        float4 v = ((const float4*)wv)[i];
        uint32_t h0, l0, h1, l1;
        split2(v.x, v.y, h0, l0);
        split2(v.z, v.w, h1, l1);
        size_t o = (size_t)row * NQKV + 2176 + col;
        *(uint2*)(wh + o) = make_uint2(h0, h1);
        *(uint2*)(wl + o) = make_uint2(l0, l1);
    } else if (blk < 16896) {             // wo: contiguous
        int i = (blk - 12800) * 256 + tid;
        float4 v = ((const float4*)wo)[i];
        uint32_t h0, l0, h1, l1;
        split2(v.x, v.y, h0, l0);
        split2(v.z, v.w, h1, l1);
        ((uint2*)woh)[i] = make_uint2(h0, h1);
        ((uint2*)wol)[i] = make_uint2(l0, l1);
    } else {                              // bias pack
        int i = (blk - 16896) * 256 + tid;
        if (i < 2048)      bias[i] = qb[i];
        else if (i < 2176) bias[i] = kb[i - 2048];
        else if (i < 2304) bias[i] = vb[i - 2176];
    }
}

// ---------------------------------------------------------------------------
// Shared GEMM tile machinery: BM=128 BN=128 BK=32, 256 thr, cp.async 3-stage.
// ---------------------------------------------------------------------------
#define STG_BYTES 32768
#define G2SMEM (3 * STG_BYTES)
#define NITER (KTOT / 32)   // 64

__device__ __forceinline__ uint32_t a_off(int r, int c) {
    return (uint32_t)(r * 64 + ((c ^ ((r >> 1) & 3)) << 4));
}
__device__ __forceinline__ uint32_t b_off(int r, int c) {
    return (uint32_t)(r * 256 + ((c ^ (r & 7)) << 4));
}

__device__ __forceinline__ void g2s_issue(
    uint32_t stg, const bf16* __restrict__ Ah, const bf16* __restrict__ Al,
    const bf16* __restrict__ Wh, const bf16* __restrict__ Wl,
    int N, int m0, int n0, int k0, int tid)
{
#pragma unroll
    for (int p = 0; p < 2; p++) {
        int cid = p * 256 + tid;
        int r = cid >> 2, c = cid & 3;
        size_t gs = (size_t)(m0 + r) * KTOT + k0 + c * 8;
        uint32_t off = a_off(r, c);
        CP16(stg + off, Ah + gs);
        CP16(stg + 8192 + off, Al + gs);
    }
#pragma unroll
    for (int p = 0; p < 2; p++) {
        int cid = p * 256 + tid;
        int r = cid >> 4, c = cid & 15;
        size_t gs = (size_t)(k0 + r) * N + n0 + c * 8;
        uint32_t off = b_off(r, c);
        CP16(stg + 16384 + off, Wh + gs);
        CP16(stg + 24576 + off, Wl + gs);
    }
}

__device__ __forceinline__ void gemm_mainloop(
    uint32_t sb, const bf16* Ah, const bf16* Al, const bf16* Wh, const bf16* Wl,
    int N, int m0, int n0, int tid, int lane, int wm, int wn, float acc[2][8][4])
{
    const int lrow = lane & 15;
    const int lsel = lane >> 4;

    g2s_issue(sb, Ah, Al, Wh, Wl, N, m0, n0, 0, tid);
    CP_COMMIT();
    g2s_issue(sb + STG_BYTES, Ah, Al, Wh, Wl, N, m0, n0, 32, tid);
    CP_COMMIT();

    for (int it = 0; it < NITER; it++) {
        if (it == NITER - 1) CP_WAIT(0); else CP_WAIT(1);
        __syncthreads();
        if (it + 2 < NITER) {
            g2s_issue(sb + ((it + 2) % 3) * STG_BYTES, Ah, Al, Wh, Wl, N,
                      m0, n0, (it + 2) * 32, tid);
            CP_COMMIT();
        }

        const uint32_t stA = sb + (uint32_t)(it % 3) * STG_BYTES;
        const uint32_t stB = stA + 16384;

#pragma unroll
        for (int ks = 0; ks < 2; ks++) {
            uint32_t ah[2][4], al[2][4];
#pragma unroll
            for (int mf = 0; mf < 2; mf++) {
                int row = wm * 32 + mf * 16 + lrow;
                int chunk = ks * 2 + lsel;
                uint32_t addr = stA + a_off(row, chunk);
                LDSM_X4(ah[mf][0], ah[mf][1], ah[mf][2], ah[mf][3], addr);
                LDSM_X4(al[mf][0], al[mf][1], al[mf][2], al[mf][3], addr + 8192);
            }
#pragma unroll
            for (int nj = 0; nj < 4; nj++) {
                int brow = ks * 16 + lrow;
                int bchunk = wn * 8 + nj * 2 + lsel;
                uint32_t baddr = stB + b_off(brow, bchunk);
                uint32_t bh[4], bl[4];
                LDSM_X4_T(bh[0], bh[1], bh[2], bh[3], baddr);
                LDSM_X4_T(bl[0], bl[1], bl[2], bl[3], baddr + 8192);
#pragma unroll
                for (int mf = 0; mf < 2; mf++) {
                    MMA_BF16(acc[mf][2 * nj],     ah[mf], bh[0], bh[1]);
                    MMA_BF16(acc[mf][2 * nj],     ah[mf], bl[0], bl[1]);
                    MMA_BF16(acc[mf][2 * nj],     al[mf], bh[0], bh[1]);
                    MMA_BF16(acc[mf][2 * nj + 1], ah[mf], bh[2], bh[3]);
                    MMA_BF16(acc[mf][2 * nj + 1], ah[mf], bl[2], bl[3]);
                    MMA_BF16(acc[mf][2 * nj + 1], al[mf], bh[2], bh[3]);
                }
            }
        }
    }
}

// ---------------------------------------------------------------------------
// Fused QKV GEMM: Out = x @ [wq|wk|wv] + bias over N=2304.
// CTA-x 0..15 -> Q (RoPE+scale*log2e, [B,H,T,D]); 16 -> K (RoPE); 17 -> V.
// ---------------------------------------------------------------------------
__global__ __launch_bounds__(256, 2)
void gemm_qkv(const bf16* __restrict__ Ah, const bf16* __restrict__ Al,
              const bf16* __restrict__ Wh, const bf16* __restrict__ Wl,
              const float* __restrict__ bias,
              bf16* __restrict__ Qh, bf16* __restrict__ Ql,
              bf16* __restrict__ Kh, bf16* __restrict__ Kl,
              bf16* __restrict__ Vh, bf16* __restrict__ Vl,
              const float* __restrict__ cs, const float* __restrict__ sn)
{
    extern __shared__ char sm[];
    const uint32_t sb = smem_u32(sm);
    const int tid  = threadIdx.x;
    const int lane = tid & 31;
    const int wid  = tid >> 5;
    const int wm   = wid >> 1;
    const int wn   = wid & 1;
    const int bxid = blockIdx.x;
    const int m0   = blockIdx.y * 128;
    const int n0   = bxid * 128;

    float acc[2][8][4];
#pragma unroll
    for (int i = 0; i < 2; i++)
#pragma unroll
        for (int j = 0; j < 8; j++)
#pragma unroll
            for (int q = 0; q < 4; q++) acc[i][j][q] = 0.f;

    gemm_mainloop(sb, Ah, Al, Wh, Wl, NQKV, m0, n0, tid, lane, wm, wn, acc);

    const int g = lane >> 2, t = lane & 3;
#pragma unroll
    for (int mf = 0; mf < 2; mf++) {
        int row0 = m0 + wm * 32 + mf * 16 + g;
#pragma unroll
        for (int nt = 0; nt < 8; nt++) {
            int col = n0 + wn * 64 + nt * 8 + 2 * t;
            float2 bi = *(const float2*)(bias + col);
            float a0 = acc[mf][nt][0] + bi.x, a1 = acc[mf][nt][1] + bi.y;
            float a2 = acc[mf][nt][2] + bi.x, a3 = acc[mf][nt][3] + bi.y;
            if (bxid < 16) {
                int f = (col & 127) >> 1;
#pragma unroll
                for (int rr = 0; rr < 2; rr++) {
                    int r = row0 + rr * 8;
                    int tloc = r & (TT - 1);
                    float c = cs[tloc * 64 + f], s = sn[tloc * 64 + f];
                    float re = rr ? a2 : a0, im = rr ? a3 : a1;
                    float ore = (re * c - im * s) * QSCALE;
                    float oim = (re * s + im * c) * QSCALE;
                    uint32_t hi, lo;
                    split2(ore, oim, hi, lo);
                    int bq = r >> 11, hq = col >> 7;
                    size_t idx = ((size_t)(bq * HH + hq) * TT + tloc) * DD + (col & 127);
                    *(uint32_t*)(Qh + idx) = hi;
                    *(uint32_t*)(Ql + idx) = lo;
                }
            } else if (bxid == 16) {
                int colp = col - 2048;
                int f = colp >> 1;
#pragma unroll
                for (int rr = 0; rr < 2; rr++) {
                    int r = row0 + rr * 8;
                    int tloc = r & (TT - 1);
                    float c = cs[tloc * 64 + f], s = sn[tloc * 64 + f];
                    float re = rr ? a2 : a0, im = rr ? a3 : a1;
                    float ore = re * c - im * s;
                    float oim = re * s + im * c;
                    uint32_t hi, lo;
                    split2(ore, oim, hi, lo);
                    size_t idx = (size_t)r * DD + colp;
                    *(uint32_t*)(Kh + idx) = hi;
                    *(uint32_t*)(Kl + idx) = lo;
                }
            } else {
                int colp = col - 2176;
                uint32_t hi, lo;
                split2(a0, a1, hi, lo);
                *(uint32_t*)(Vh + (size_t)row0 * DD + colp) = hi;
                *(uint32_t*)(Vl + (size_t)row0 * DD + colp) = lo;
                split2(a2, a3, hi, lo);
                *(uint32_t*)(Vh + (size_t)(row0 + 8) * DD + colp) = hi;
                *(uint32_t*)(Vl + (size_t)(row0 + 8) * DD + colp) = lo;
            }
        }
    }
}

// ---------------------------------------------------------------------------
// Output GEMM: out = O @ wo + bias (fp32 out, N=2048)
// ---------------------------------------------------------------------------
__global__ __launch_bounds__(256, 2)
void gemm_out(const bf16* __restrict__ Ah, const bf16* __restrict__ Al,
              const bf16* __restrict__ Wh, const bf16* __restrict__ Wl,
              const float* __restrict__ bias, float* __restrict__ OutF)
{
    extern __shared__ char sm[];
    const uint32_t sb = smem_u32(sm);
    const int tid  = threadIdx.x;
    const int lane = tid & 31;
    const int wid  = tid >> 5;
    const int wm   = wid >> 1;
    const int wn   = wid & 1;
    const int m0   = blockIdx.y * 128;
    const int n0   = blockIdx.x * 128;

    float acc[2][8][4];
#pragma unroll
    for (int i = 0; i < 2; i++)
#pragma unroll
        for (int j = 0; j < 8; j++)
#pragma unroll
            for (int q = 0; q < 4; q++) acc[i][j][q] = 0.f;

    gemm_mainloop(sb, Ah, Al, Wh, Wl, CC, m0, n0, tid, lane, wm, wn, acc);

    const int g = lane >> 2, t = lane & 3;
#pragma unroll
    for (int mf = 0; mf < 2; mf++) {
        int row0 = m0 + wm * 32 + mf * 16 + g;
#pragma unroll
        for (int nt = 0; nt < 8; nt++) {
            int col = n0 + wn * 64 + nt * 8 + 2 * t;
            float2 bi = *(const float2*)(bias + col);
            *(float2*)(OutF + (size_t)row0 * CC + col) =
                make_float2(acc[mf][nt][0] + bi.x, acc[mf][nt][1] + bi.y);
            *(float2*)(OutF + (size_t)(row0 + 8) * CC + col) =
                make_float2(acc[mf][nt][2] + bi.x, acc[mf][nt][3] + bi.y);
        }
    }
}

// ---------------------------------------------------------------------------
// Flash attention on mma.sync: BM=64 (4 warps x 16 rows), BN=32, D=128.
// 96KB smem -> 2 CTAs/SM. Softmax in base-2 (Q pre-scaled by log2e).
// smem: Qh 16K | Ql 16K | stage s: Kh 8K Kl 8K Vh 8K Vl 8K (2 stages)
// ---------------------------------------------------------------------------
#define AQ_L 16384u
#define AKV(s) (32768u + (uint32_t)(s) * 32768u)
#define A_SMEM 98304

__device__ __forceinline__ uint32_t toff(int r, int c) {
    return (uint32_t)(r * 256 + ((c ^ (r & 7)) << 4));
}

__global__ __launch_bounds__(128, 2) void attn_mma(
    const bf16* __restrict__ Qh, const bf16* __restrict__ Ql,
    const bf16* __restrict__ Kh, const bf16* __restrict__ Kl,
    const bf16* __restrict__ Vh, const bf16* __restrict__ Vl,
    bf16* __restrict__ Oh, bf16* __restrict__ Ol)
{
    extern __shared__ char sm[];
    const uint32_t sb = smem_u32(sm);
    const int tid = threadIdx.x, lane = tid & 31, w = tid >> 5;
    const int id = blockIdx.x;
    const int bx = (TT / 64 - 1) - (id >> 5);   // heavy-first
    const int hb = id & 31;
    const int h  = hb & 15;
    const int b  = hb >> 4;
    const int i0 = bx * 64;
    const int jtmax = 2 * bx + 1;               // BN=32 tiles

    const size_t qbase  = ((size_t)(b * HH + h) * TT + i0) * DD;
    const size_t kvbase = (size_t)b * TT * DD;

    // Q tile (64 rows) + KV stage 0 (32 rows)
#pragma unroll
    for (int i = 0; i < 8; i++) {
        int cid = i * 128 + tid;
        int r = cid >> 4, c = cid & 15;
        size_t gs = qbase + (size_t)r * DD + c * 8;
        uint32_t off = toff(r, c);
        CP16(sb + off, Qh + gs);
        CP16(sb + AQ_L + off, Ql + gs);
    }
#pragma unroll
    for (int i = 0; i < 4; i++) {
        int cid = i * 128 + tid;
        int r = cid >> 4, c = cid & 15;
        size_t gs = kvbase + (size_t)r * DD + c * 8;
        uint32_t off = toff(r, c);
        CP16(sb + AKV(0) + off,          Kh + gs);
        CP16(sb + AKV(0) + 8192 + off,   Kl + gs);
        CP16(sb + AKV(0) + 16384 + off,  Vh + gs);
        CP16(sb + AKV(0) + 24576 + off,  Vl + gs);
    }
    CP_COMMIT();

    const int lrA = lane & 15;
    const int lsA = lane >> 4;
    const int lrB = (lane & 7) + ((lane >> 4) << 3);
    const int csB = (lane >> 3) & 1;
    const int g = lane >> 2, t = lane & 3;

    float oa[16][4];
#pragma unroll
    for (int i = 0; i < 16; i++)
#pragma unroll
        for (int j = 0; j < 4; j++) oa[i][j] = 0.f;
    float m0r = -1e30f, m1r = -1e30f, l0r = 0.f, l1r = 0.f;

    for (int jt = 0; jt <= jtmax; jt++) {
        if (jt > 0) __syncthreads();
        if (jt + 1 <= jtmax) {
            uint32_t stg = AKV((jt + 1) & 1);
#pragma unroll
            for (int i = 0; i < 4; i++) {
                int cid = i * 128 + tid;
                int r = cid >> 4, c = cid & 15;
                size_t gs = kvbase + (size_t)((jt + 1) * 32 + r) * DD + c * 8;
                uint32_t off = toff(r, c);
                CP16(sb + stg + off,          Kh + gs);
                CP16(sb + stg + 8192 + off,   Kl + gs);
                CP16(sb + stg + 16384 + off,  Vh + gs);
                CP16(sb + stg + 24576 + off,  Vl + gs);
            }
            CP_COMMIT();
            CP_WAIT(1);
        } else {
            CP_WAIT(0);
        }
        __syncthreads();

        // fully-masked tile for this warp's 16-row strip?
        if (32 * jt > i0 + 16 * w + 15) continue;

        const uint32_t kvs = sb + AKV(jt & 1);

        // ---- S = Q K^T (4 n-frags = 32 cols) ----
        float sa[4][4];
#pragma unroll
        for (int i = 0; i < 4; i++)
#pragma unroll
            for (int j = 0; j < 4; j++) sa[i][j] = 0.f;

#pragma unroll
        for (int ks = 0; ks < 8; ks++) {
            uint32_t ah[4], al[4];
            uint32_t qaddr = sb + toff(16 * w + lrA, 2 * ks + lsA);
            LDSM_X4(ah[0], ah[1], ah[2], ah[3], qaddr);
            LDSM_X4(al[0], al[1], al[2], al[3], qaddr + AQ_L);
#pragma unroll
            for (int np = 0; np < 2; np++) {
                uint32_t kaddr = kvs + toff(np * 16 + lrB, 2 * ks + csB);
                uint32_t bh[4], bl[4];
                LDSM_X4(bh[0], bh[1], bh[2], bh[3], kaddr);
                LDSM_X4(bl[0], bl[1], bl[2], bl[3], kaddr + 8192);
                MMA_BF16(sa[2 * np],     ah, bh[0], bh[1]);
                MMA_BF16(sa[2 * np],     ah, bl[0], bl[1]);
                MMA_BF16(sa[2 * np],     al, bh[0], bh[1]);
                MMA_BF16(sa[2 * np + 1], ah, bh[2], bh[3]);
                MMA_BF16(sa[2 * np + 1], ah, bl[2], bl[3]);
                MMA_BF16(sa[2 * np + 1], al, bh[2], bh[3]);
            }
        }

        // ---- causal mask ----
        if (32 * jt + 31 > i0 + 16 * w) {
            int r0g = i0 + 16 * w + g;
#pragma unroll
            for (int nf = 0; nf < 4; nf++) {
                int cg = 32 * jt + nf * 8 + 2 * t;
                if (cg     > r0g)     sa[nf][0] = -1e30f;
                if (cg + 1 > r0g)     sa[nf][1] = -1e30f;
                if (cg     > r0g + 8) sa[nf][2] = -1e30f;
                if (cg + 1 > r0g + 8) sa[nf][3] = -1e30f;
            }
        }

        // ---- online softmax (base-2) ----
        float mx0 = -1e30f, mx1 = -1e30f;
#pragma unroll
        for (int nf = 0; nf < 4; nf++) {
            mx0 = fmaxf(mx0, fmaxf(sa[nf][0], sa[nf][1]));
            mx1 = fmaxf(mx1, fmaxf(sa[nf][2], sa[nf][3]));
        }
        mx0 = fmaxf(mx0, __shfl_xor_sync(0xffffffffu, mx0, 1));
        mx0 = fmaxf(mx0, __shfl_xor_sync(0xffffffffu, mx0, 2));
        mx1 = fmaxf(mx1, __shfl_xor_sync(0xffffffffu, mx1, 1));
        mx1 = fmaxf(mx1, __shfl_xor_sync(0xffffffffu, mx1, 2));
        float mn0 = fmaxf(m0r, mx0), mn1 = fmaxf(m1r, mx1);

        float sum0 = 0.f, sum1 = 0.f;
#pragma unroll
        for (int nf = 0; nf < 4; nf++) {
            sa[nf][0] = ex2(sa[nf][0] - mn0);
            sa[nf][1] = ex2(sa[nf][1] - mn0);
            sa[nf][2] = ex2(sa[nf][2] - mn1);
            sa[nf][3] = ex2(sa[nf][3] - mn1);
            sum0 += sa[nf][0] + sa[nf][1];
            sum1 += sa[nf][2] + sa[nf][3];
        }
        sum0 += __shfl_xor_sync(0xffffffffu, sum0, 1);
        sum0 += __shfl_xor_sync(0xffffffffu, sum0, 2);
        sum1 += __shfl_xor_sync(0xffffffffu, sum1, 1);
        sum1 += __shfl_xor_sync(0xffffffffu, sum1, 2);

        float scl0 = ex2(m0r - mn0), scl1 = ex2(m1r - mn1);
        l0r = l0r * scl0 + sum0;
        l1r = l1r * scl1 + sum1;
        m0r = mn0; m1r = mn1;

#pragma unroll
        for (int nf = 0; nf < 16; nf++) {
            oa[nf][0] *= scl0; oa[nf][1] *= scl0;
            oa[nf][2] *= scl1; oa[nf][3] *= scl1;
        }

        // ---- O += P V ----
#pragma unroll
        for (int s = 0; s < 2; s++) {
            uint32_t aPh[4], aPl[4];
            split2(sa[2 * s][0],     sa[2 * s][1],     aPh[0], aPl[0]);
            split2(sa[2 * s][2],     sa[2 * s][3],     aPh[1], aPl[1]);
            split2(sa[2 * s + 1][0], sa[2 * s + 1][1], aPh[2], aPl[2]);
            split2(sa[2 * s + 1][2], sa[2 * s + 1][3], aPh[3], aPl[3]);
#pragma unroll
            for (int np = 0; np < 8; np++) {
                uint32_t vaddr = kvs + 16384 + toff(s * 16 + lrA, 2 * np + lsA);
                uint32_t bh[4], bl[4];
                LDSM_X4_T(bh[0], bh[1], bh[2], bh[3], vaddr);
                LDSM_X4_T(bl[0], bl[1], bl[2], bl[3], vaddr + 8192);
                MMA_BF16(oa[2 * np],     aPh, bh[0], bh[1]);
                MMA_BF16(oa[2 * np],     aPh, bl[0], bl[1]);
                MMA_BF16(oa[2 * np],     aPl, bh[0], bh[1]);
                MMA_BF16(oa[2 * np + 1], aPh, bh[2], bh[3]);
                MMA_BF16(oa[2 * np + 1], aPh, bl[2], bl[3]);
                MMA_BF16(oa[2 * np + 1], aPl, bh[2], bh[3]);
            }
        }
    }

    // ---- epilogue ----
    float inv0 = 1.f / l0r, inv1 = 1.f / l1r;
    size_t or0 = (size_t)(b * TT + i0 + 16 * w + g) * CC + h * DD;
    size_t or1 = or0 + (size_t)8 * CC;
#pragma unroll
    for (int nf = 0; nf < 16; nf++) {
        int col = nf * 8 + 2 * t;
        uint32_t hi, lo;
        split2(oa[nf][0] * inv0, oa[nf][1] * inv0, hi, lo);
        *(uint32_t*)(Oh + or0 + col) = hi;
        *(uint32_t*)(Ol + or0 + col) = lo;
        split2(oa[nf][2] * inv1, oa[nf][3] * inv1, hi, lo);
        *(uint32_t*)(Oh + or1 + col) = hi;
        *(uint32_t*)(Ol + or1 + col) = lo;
    }
}

// ---------------------------------------------------------------------------
// Launcher
// ---------------------------------------------------------------------------
extern "C" void kernel_launch(void* const* d_in, const int* in_sizes, int n_in,
                              void* d_out, int out_size)
{
    const float* x    = (const float*)d_in[0];
    const float* fcos = (const float*)d_in[1];
    const float* fsin = (const float*)d_in[2];
    const float* wq   = (const float*)d_in[4];
    const float* wqb  = (const float*)d_in[5];
    const float* wk   = (const float*)d_in[6];
    const float* wkb  = (const float*)d_in[7];
    const float* wv   = (const float*)d_in[8];
    const float* wvb  = (const float*)d_in[9];
    const float* wo   = (const float*)d_in[10];
    const float* wob  = (const float*)d_in[11];
    float* out = (float*)d_out;

    bf16 *xh, *xl, *wh, *wl, *woh, *wol;
    bf16 *Qhp, *Qlp, *Khp, *Klp, *Vhp, *Vlp, *Ohp, *Olp;
    float* biasp;
    cudaGetSymbolAddress((void**)&xh, g_xh);   cudaGetSymbolAddress((void**)&xl, g_xl);
    cudaGetSymbolAddress((void**)&wh, g_wh);   cudaGetSymbolAddress((void**)&wl, g_wl);
    cudaGetSymbolAddress((void**)&woh, g_woh); cudaGetSymbolAddress((void**)&wol, g_wol);
    cudaGetSymbolAddress((void**)&biasp, g_bias);
    cudaGetSymbolAddress((void**)&Qhp, g_Qh);  cudaGetSymbolAddress((void**)&Qlp, g_Ql);
    cudaGetSymbolAddress((void**)&Khp, g_Kh);  cudaGetSymbolAddress((void**)&Klp, g_Kl);
    cudaGetSymbolAddress((void**)&Vhp, g_Vh);  cudaGetSymbolAddress((void**)&Vlp, g_Vl);
    cudaGetSymbolAddress((void**)&Ohp, g_Oh);  cudaGetSymbolAddress((void**)&Olp, g_Ol);

    cudaFuncSetAttribute(gemm_qkv, cudaFuncAttributeMaxDynamicSharedMemorySize, G2SMEM);
    cudaFuncSetAttribute(gemm_out, cudaFuncAttributeMaxDynamicSharedMemorySize, G2SMEM);
    cudaFuncSetAttribute(attn_mma, cudaFuncAttributeMaxDynamicSharedMemorySize, A_SMEM);

    // 1. single merged prep launch
    prep_kernel<<<16905, 256>>>(x, wq, wk, wv, wo, wqb, wkb, wvb,
                                xh, xl, wh, wl, woh, wol, biasp);

    // 2. fused QKV projection
    gemm_qkv<<<dim3(NQKV / 128, MTOT / 128), 256, G2SMEM>>>(
        xh, xl, wh, wl, biasp, Qhp, Qlp, Khp, Klp, Vhp, Vlp, fcos, fsin);

    // 3. flash attention (BM=64, 2 CTAs/SM, heavy-first)
    attn_mma<<<1024, 128, A_SMEM>>>(Qhp, Qlp, Khp, Klp, Vhp, Vlp, Ohp, Olp);

    // 4. output projection -> d_out
    gemm_out<<<dim3(CC / 128, MTOT / 128), 256, G2SMEM>>>(
        Ohp, Olp, woh, wol, wob, out);
}